// round 12
// baseline (speedup 1.0000x reference)
#include <cuda_runtime.h>
#include <cuda_fp16.h>
#include <cstdint>
#include <math.h>

// Problem constants
constexpr int B_  = 4;
constexpr int S_  = 2048;
constexpr int D_  = 1024;
constexpr int H_  = 16;
constexpr int DK_ = 64;
constexpr int M_  = B_ * S_;   // 8192

// Scratch (device globals — no allocation allowed)
__device__ __half g_qh[(size_t)B_ * H_ * S_ * DK_];   // [B,H,S,DK]
__device__ __half g_kh[(size_t)B_ * H_ * S_ * DK_];
__device__ __half g_vh[(size_t)B_ * H_ * S_ * DK_];
__device__ float  g_ctx[(size_t)B_ * S_ * D_];        // [B,S,D] fp32

// ---------------------------------------------------------------------------
// helpers (all non-suffixed PTX: works under generic sm_103 target)
// ---------------------------------------------------------------------------
__device__ __forceinline__ void mma_f16_16n8k16(float* c, const uint32_t* a,
                                                uint32_t b0, uint32_t b1) {
    asm volatile(
        "mma.sync.aligned.m16n8k16.row.col.f32.f16.f16.f32 "
        "{%0,%1,%2,%3}, {%4,%5,%6,%7}, {%8,%9}, {%0,%1,%2,%3};"
        : "+f"(c[0]), "+f"(c[1]), "+f"(c[2]), "+f"(c[3])
        : "r"(a[0]), "r"(a[1]), "r"(a[2]), "r"(a[3]), "r"(b0), "r"(b1));
}

__device__ __forceinline__ uint32_t smem_u32(const void* p) {
    uint32_t a;
    asm("{ .reg .u64 t; cvta.to.shared.u64 t, %1; cvt.u32.u64 %0, t; }"
        : "=r"(a) : "l"(p));
    return a;
}
__device__ __forceinline__ void cp_async16(uint32_t saddr, const void* g) {
    asm volatile("cp.async.ca.shared.global [%0], [%1], 16;"
                 :: "r"(saddr), "l"(g));
}
#define CP_COMMIT() asm volatile("cp.async.commit_group;" ::: "memory")
#define CP_WAIT0()  asm volatile("cp.async.wait_group 0;" ::: "memory")
#define CP_WAIT1()  asm volatile("cp.async.wait_group 1;" ::: "memory")

__device__ __forceinline__ void ldsm_x4(uint32_t& r0, uint32_t& r1,
                                        uint32_t& r2, uint32_t& r3,
                                        uint32_t addr) {
    asm volatile("ldmatrix.sync.aligned.m8n8.x4.shared.b16 {%0,%1,%2,%3}, [%4];"
                 : "=r"(r0), "=r"(r1), "=r"(r2), "=r"(r3) : "r"(addr));
}
__device__ __forceinline__ void ldsm_x4_trans(uint32_t& r0, uint32_t& r1,
                                              uint32_t& r2, uint32_t& r3,
                                              uint32_t addr) {
    asm volatile("ldmatrix.sync.aligned.m8n8.x4.trans.shared.b16 {%0,%1,%2,%3}, [%4];"
                 : "=r"(r0), "=r"(r1), "=r"(r2), "=r"(r3) : "r"(addr));
}

// ---------------------------------------------------------------------------
// FP16 tensor-core GEMM: Y[M,N] = X @ W^T + bias  (fp32 in, fp32 accumulate).
// BM=BN=128, BK=16, 256 threads, 8 warps (4x2), warp tile 32x64.
// m16n8k16 HMMA (2x FLOP/instr vs tf32 k8); fragments via ldmatrix with the
// lane mappings proven in flash_f16. Row stride 48B: ldsm phases hit quads
// 3r mod 8 (distinct); fill mapping gives conflict-free STS.128.
// which: 0/1/2 -> g_qh/g_kh/g_vh fp16 split-head; 3 -> read g_ctx, fp32 dst.
// ---------------------------------------------------------------------------
constexpr int LDGH = 24;              // halves per smem row (48 B)
constexpr int GST  = 128 * LDGH;      // halves per tensor per stage

__global__ __launch_bounds__(256, 2) void gemm_f16(
    const float* __restrict__ X, const float* __restrict__ W,
    const float* __restrict__ bias, float* __restrict__ dst, int which)
{
    __shared__ __half As[2][GST];
    __shared__ __half Bs[2][GST];

    const int tid = threadIdx.x;
    const int wid = tid >> 5;
    const int lane = tid & 31;
    const int m0 = blockIdx.y * 128;
    const int n0 = blockIdx.x * 128;
    const int warp_m = (wid & 3) * 32;
    const int warp_n = (wid >> 2) * 64;

    const float* Xin = (which == 3) ? (const float*)g_ctx : X;

    // Fill mapping: row = 8*(tid>>4) + (tid&7) in 0..127; col-half c in {0,1}.
    // 8-lane STS phases cover 8 consecutive rows, same c -> distinct quads.
    const int frow = ((tid >> 4) << 3) | (tid & 7);
    const int fc   = (tid >> 3) & 1;

    const float* gA = Xin + (size_t)(m0 + frow) * D_ + fc * 8;
    const float* gB = W + (size_t)(n0 + frow) * D_ + fc * 8;
    const int soff = frow * LDGH + fc * 8;

    float acc[2][8][4];
#pragma unroll
    for (int i = 0; i < 2; i++)
#pragma unroll
        for (int j = 0; j < 8; j++)
#pragma unroll
            for (int r = 0; r < 4; r++) acc[i][j][r] = 0.f;

    float4 pa0, pa1, pb0, pb1;

    auto ldg = [&](int t) {
        const float* a = gA + t * 16;
        pa0 = *(const float4*)a;
        pa1 = *(const float4*)(a + 4);
        const float* b = gB + t * 16;
        pb0 = *(const float4*)b;
        pb1 = *(const float4*)(b + 4);
    };
    auto sts = [&](int s) {
        __half2 t0 = __floats2half2_rn(pa0.x, pa0.y);
        __half2 t1 = __floats2half2_rn(pa0.z, pa0.w);
        __half2 t2 = __floats2half2_rn(pa1.x, pa1.y);
        __half2 t3 = __floats2half2_rn(pa1.z, pa1.w);
        uint4 ua;
        ua.x = *(uint32_t*)&t0; ua.y = *(uint32_t*)&t1;
        ua.z = *(uint32_t*)&t2; ua.w = *(uint32_t*)&t3;
        *(uint4*)&As[s][soff] = ua;
        t0 = __floats2half2_rn(pb0.x, pb0.y);
        t1 = __floats2half2_rn(pb0.z, pb0.w);
        t2 = __floats2half2_rn(pb1.x, pb1.y);
        t3 = __floats2half2_rn(pb1.z, pb1.w);
        uint4 ub;
        ub.x = *(uint32_t*)&t0; ub.y = *(uint32_t*)&t1;
        ub.z = *(uint32_t*)&t2; ub.w = *(uint32_t*)&t3;
        *(uint4*)&Bs[s][soff] = ub;
    };

    ldg(0);
    sts(0);
    __syncthreads();

    // ldsm lane mappings (bytes), strides 48B — proven in flash_f16 (144B).
    const int lm = lane >> 3;
    const int lr7 = lane & 7;
    const uint32_t laneA =
        (uint32_t)(((lm & 1) * 8 + lr7) * 48 + (lm >> 1) * 16);
    const uint32_t laneB =
        (uint32_t)(((lm >> 1) * 8 + lr7) * 48 + (lm & 1) * 16);

    const uint32_t saA[2] = { smem_u32(&As[0][0]), smem_u32(&As[1][0]) };
    const uint32_t saB[2] = { smem_u32(&Bs[0][0]), smem_u32(&Bs[1][0]) };

    for (int t = 0; t < D_ / 16; t++) {
        int s = t & 1;
        if (t < D_ / 16 - 1) ldg(t + 1);

        uint32_t a[2][4];
        ldsm_x4(a[0][0], a[0][1], a[0][2], a[0][3],
                saA[s] + (uint32_t)(warp_m * 48) + laneA);
        ldsm_x4(a[1][0], a[1][1], a[1][2], a[1][3],
                saA[s] + (uint32_t)((warp_m + 16) * 48) + laneA);
#pragma unroll
        for (int jnp = 0; jnp < 4; jnp++) {
            uint32_t b0, b1, b2, b3;
            ldsm_x4(b0, b1, b2, b3,
                    saB[s] + (uint32_t)((warp_n + 16 * jnp) * 48) + laneB);
            mma_f16_16n8k16(acc[0][2 * jnp], a[0], b0, b1);
            mma_f16_16n8k16(acc[1][2 * jnp], a[1], b0, b1);
            mma_f16_16n8k16(acc[0][2 * jnp + 1], a[0], b2, b3);
            mma_f16_16n8k16(acc[1][2 * jnp + 1], a[1], b2, b3);
        }

        if (t < D_ / 16 - 1) sts(s ^ 1);
        __syncthreads();
    }

    const int r8 = lane >> 2;
    const int c2 = (lane & 3) * 2;
#pragma unroll
    for (int im = 0; im < 2; im++) {
#pragma unroll
        for (int jn = 0; jn < 8; jn++) {
            int n = n0 + warp_n + 8 * jn + c2;
            float bx = bias[n], by = bias[n + 1];
            int mA = m0 + warp_m + 16 * im + r8;
            int mB = mA + 8;
            float2 v0 = make_float2(acc[im][jn][0] + bx, acc[im][jn][1] + by);
            float2 v1 = make_float2(acc[im][jn][2] + bx, acc[im][jn][3] + by);
            if (which < 3) {
                __half* outh = (which == 0) ? g_qh : (which == 1) ? g_kh : g_vh;
                __half2 h0 = __floats2half2_rn(v0.x, v0.y);
                __half2 h1 = __floats2half2_rn(v1.x, v1.y);
                int h = n >> 6, dk = n & 63;
                int bA = mA >> 11, sA = mA & (S_ - 1);
                int bB = mB >> 11, sB = mB & (S_ - 1);
                *(__half2*)&outh[(((size_t)(bA * H_ + h) * S_ + sA) << 6) + dk] = h0;
                *(__half2*)&outh[(((size_t)(bB * H_ + h) * S_ + sB) << 6) + dk] = h1;
            } else {
                *(float2*)&dst[(size_t)mA * D_ + n] = v0;
                *(float2*)&dst[(size_t)mB * D_ + n] = v1;
            }
        }
    }
}

// ---------------------------------------------------------------------------
// Flash attention v6 (fp16 m16n8k16) — UNCHANGED from R11 (proven 268us).
// ---------------------------------------------------------------------------
constexpr int LDH    = 72;            // halves per row (144 B)
constexpr int QBYTES = 256 * 144;
constexpr int KSTAGE = 64 * 144;
constexpr int VSTAGE = 64 * 144;
constexpr int PBYTES = 256 * 144;
constexpr int FSMEM  = QBYTES + 2 * KSTAGE + 2 * VSTAGE + PBYTES;  // 110592

__global__ __launch_bounds__(256, 1) void flash_f16()
{
    extern __shared__ char smc[];
    char* sQ = smc;
    char* sK = sQ + QBYTES;
    char* sV = sK + 2 * KSTAGE;
    char* sP = sV + 2 * VSTAGE;

    const uint32_t sqb = smem_u32(sQ);
    const uint32_t skb = smem_u32(sK);
    const uint32_t svb = smem_u32(sV);
    const uint32_t spb = smem_u32(sP);
    __half* sPh = (__half*)sP;

    const int tid = threadIdx.x;
    const int wid = tid >> 5;
    const int lane = tid & 31;
    const int r8 = lane >> 2;
    const int c4 = lane & 3;
    const int lm = lane >> 3;
    const int lr7 = lane & 7;

    const uint32_t laneA =
        (uint32_t)(((lm & 1) * 8 + lr7) * 144 + (lm >> 1) * 16);
    const uint32_t laneB =
        (uint32_t)(((lm >> 1) * 8 + lr7) * 144 + (lm & 1) * 16);
    const uint32_t laneV =
        (uint32_t)(((lm & 1) * 8 + lr7) * 144 + (lm >> 1) * 16);

    const int q0 = blockIdx.x * 256;
    const int h = blockIdx.y;
    const int b = blockIdx.z;
    const size_t base = (size_t)(b * H_ + h) * S_ * DK_;
    const __half* qg = g_qh + base + (size_t)q0 * DK_;
    const __half* kg = g_kh + base;
    const __half* vg = g_vh + base;

    const int wr = wid * 32;

    auto issue_chunk = [&](int kb, int st) {
#pragma unroll
        for (int i = 0; i < 2; i++) {
            int idx = tid + i * 256;
            int row = idx >> 3;
            int c16 = (idx & 7) * 16;
            cp_async16(skb + (uint32_t)(st * KSTAGE + row * 144) + c16,
                       kg + (size_t)(kb + row) * DK_ + (idx & 7) * 8);
            cp_async16(svb + (uint32_t)(st * VSTAGE + row * 144) + c16,
                       vg + (size_t)(kb + row) * DK_ + (idx & 7) * 8);
        }
        CP_COMMIT();
    };

#pragma unroll
    for (int i = 0; i < 8; i++) {
        int idx = tid + i * 256;
        int row = idx >> 3;
        int c16 = (idx & 7) * 16;
        cp_async16(sqb + (uint32_t)(row * 144) + c16,
                   qg + (size_t)row * DK_ + (idx & 7) * 8);
    }
    CP_COMMIT();
    issue_chunk(0, 0);

    CP_WAIT1();
    __syncthreads();

    uint32_t aq[2][4][4];
    {
        const __half2 hs = __half2half2(__float2half_rn(0.125f));
#pragma unroll
        for (int t = 0; t < 2; t++) {
#pragma unroll
            for (int kc = 0; kc < 4; kc++) {
                uint32_t addr = sqb + (uint32_t)((wr + 16 * t) * 144 + kc * 32) + laneA;
                ldsm_x4(aq[t][kc][0], aq[t][kc][1], aq[t][kc][2], aq[t][kc][3], addr);
#pragma unroll
                for (int r = 0; r < 4; r++) {
                    __half2 v = *(__half2*)&aq[t][kc][r];
                    v = __hmul2(v, hs);
                    aq[t][kc][r] = *(uint32_t*)&v;
                }
            }
        }
    }

    float mrow[2][2], lrow[2][2];
    float o0[8][4], o1[8][4];
#pragma unroll
    for (int t = 0; t < 2; t++) {
        mrow[t][0] = mrow[t][1] = -1e30f;
        lrow[t][0] = lrow[t][1] = 0.f;
    }
#pragma unroll
    for (int j = 0; j < 8; j++)
#pragma unroll
        for (int r = 0; r < 4; r++) { o0[j][r] = 0.f; o1[j][r] = 0.f; }

    const uint32_t paddr0 = spb + (uint32_t)(wr * 144) + laneA;
    const uint32_t paddr1 = spb + (uint32_t)((wr + 16) * 144) + laneA;

    for (int c = 0; c < S_ / 64; c++) {
        const int st = c & 1;
        CP_WAIT0();
        __syncthreads();
        if (c + 1 < S_ / 64) issue_chunk((c + 1) * 64, st ^ 1);

        const uint32_t skc = skb + (uint32_t)(st * KSTAGE) + laneB;
        const uint32_t svc = svb + (uint32_t)(st * VSTAGE) + laneV;

        float s0[8][4], s1[8][4];
#pragma unroll
        for (int j = 0; j < 8; j++)
#pragma unroll
            for (int r = 0; r < 4; r++) { s0[j][r] = 0.f; s1[j][r] = 0.f; }

#pragma unroll
        for (int kc = 0; kc < 4; kc++) {
#pragma unroll
            for (int jnp = 0; jnp < 4; jnp++) {
                uint32_t k0, k1, k2, k3;
                ldsm_x4(k0, k1, k2, k3,
                        skc + (uint32_t)(jnp * 16 * 144 + kc * 32));
                mma_f16_16n8k16(s0[2 * jnp], aq[0][kc], k0, k1);
                mma_f16_16n8k16(s1[2 * jnp], aq[1][kc], k0, k1);
                mma_f16_16n8k16(s0[2 * jnp + 1], aq[0][kc], k2, k3);
                mma_f16_16n8k16(s1[2 * jnp + 1], aq[1][kc], k2, k3);
            }
        }

#pragma unroll
        for (int t = 0; t < 2; t++) {
            float (*s)[4] = (t == 0) ? s0 : s1;
            float (*o)[4] = (t == 0) ? o0 : o1;
            float mx0 = -1e30f, mx1 = -1e30f;
#pragma unroll
            for (int jn = 0; jn < 8; jn++) {
                mx0 = fmaxf(mx0, fmaxf(s[jn][0], s[jn][1]));
                mx1 = fmaxf(mx1, fmaxf(s[jn][2], s[jn][3]));
            }
            mx0 = fmaxf(mx0, __shfl_xor_sync(0xffffffffu, mx0, 1));
            mx0 = fmaxf(mx0, __shfl_xor_sync(0xffffffffu, mx0, 2));
            mx1 = fmaxf(mx1, __shfl_xor_sync(0xffffffffu, mx1, 1));
            mx1 = fmaxf(mx1, __shfl_xor_sync(0xffffffffu, mx1, 2));
            float mn0 = fmaxf(mrow[t][0], mx0), mn1 = fmaxf(mrow[t][1], mx1);
            float alpha0 = __expf(mrow[t][0] - mn0);
            float alpha1 = __expf(mrow[t][1] - mn1);
            float sum0 = 0.f, sum1 = 0.f;
#pragma unroll
            for (int jn = 0; jn < 8; jn++) {
                s[jn][0] = __expf(s[jn][0] - mn0);
                s[jn][1] = __expf(s[jn][1] - mn0);
                s[jn][2] = __expf(s[jn][2] - mn1);
                s[jn][3] = __expf(s[jn][3] - mn1);
                sum0 += s[jn][0] + s[jn][1];
                sum1 += s[jn][2] + s[jn][3];
            }
            sum0 += __shfl_xor_sync(0xffffffffu, sum0, 1);
            sum0 += __shfl_xor_sync(0xffffffffu, sum0, 2);
            sum1 += __shfl_xor_sync(0xffffffffu, sum1, 1);
            sum1 += __shfl_xor_sync(0xffffffffu, sum1, 2);
            lrow[t][0] = lrow[t][0] * alpha0 + sum0;
            lrow[t][1] = lrow[t][1] * alpha1 + sum1;
            mrow[t][0] = mn0;
            mrow[t][1] = mn1;
#pragma unroll
            for (int jn = 0; jn < 8; jn++) {
                o[jn][0] *= alpha0; o[jn][1] *= alpha0;
                o[jn][2] *= alpha1; o[jn][3] *= alpha1;
            }
            int pr = wr + 16 * t + r8;
#pragma unroll
            for (int jn = 0; jn < 8; jn++) {
                *(__half2*)&sPh[pr * LDH + 8 * jn + 2 * c4] =
                    __floats2half2_rn(s[jn][0], s[jn][1]);
                *(__half2*)&sPh[(pr + 8) * LDH + 8 * jn + 2 * c4] =
                    __floats2half2_rn(s[jn][2], s[jn][3]);
            }
        }
        __syncwarp();

#pragma unroll
        for (int kc = 0; kc < 4; kc++) {
            uint32_t ap0[4], ap1[4];
            ldsm_x4(ap0[0], ap0[1], ap0[2], ap0[3],
                    paddr0 + (uint32_t)(kc * 32));
            ldsm_x4(ap1[0], ap1[1], ap1[2], ap1[3],
                    paddr1 + (uint32_t)(kc * 32));
#pragma unroll
            for (int jnp = 0; jnp < 4; jnp++) {
                uint32_t v0, v1, v2, v3;
                ldsm_x4_trans(v0, v1, v2, v3,
                              svc + (uint32_t)(kc * 16 * 144 + jnp * 32));
                mma_f16_16n8k16(o0[2 * jnp], ap0, v0, v1);
                mma_f16_16n8k16(o1[2 * jnp], ap1, v0, v1);
                mma_f16_16n8k16(o0[2 * jnp + 1], ap0, v2, v3);
                mma_f16_16n8k16(o1[2 * jnp + 1], ap1, v2, v3);
            }
        }
        __syncwarp();
    }

#pragma unroll
    for (int t = 0; t < 2; t++) {
        float (*o)[4] = (t == 0) ? o0 : o1;
        float inv0 = 1.0f / lrow[t][0], inv1 = 1.0f / lrow[t][1];
        int row0 = q0 + wr + 16 * t + r8;
        int row1 = row0 + 8;
        size_t g0 = ((size_t)b * S_ + row0) * D_ + h * DK_;
        size_t g1 = ((size_t)b * S_ + row1) * D_ + h * DK_;
#pragma unroll
        for (int jn = 0; jn < 8; jn++) {
            int col = 8 * jn + 2 * c4;
            *(float2*)&g_ctx[g0 + col] = make_float2(o[jn][0] * inv0, o[jn][1] * inv0);
            *(float2*)&g_ctx[g1 + col] = make_float2(o[jn][2] * inv1, o[jn][3] * inv1);
        }
    }
}

// ---------------------------------------------------------------------------
// Launch
// ---------------------------------------------------------------------------
extern "C" void kernel_launch(void* const* d_in, const int* in_sizes, int n_in,
                              void* d_out, int out_size)
{
    const float* Q  = (const float*)d_in[0];
    const float* K  = (const float*)d_in[1];
    const float* V  = (const float*)d_in[2];
    const float* Wq = (const float*)d_in[3];
    const float* bq = (const float*)d_in[4];
    const float* Wk = (const float*)d_in[5];
    const float* bk = (const float*)d_in[6];
    const float* Wv = (const float*)d_in[7];
    const float* bv = (const float*)d_in[8];
    const float* Wo = (const float*)d_in[9];
    const float* bo = (const float*)d_in[10];
    float* out = (float*)d_out;

    cudaFuncSetAttribute(flash_f16,
                         cudaFuncAttributeMaxDynamicSharedMemorySize, FSMEM);

    dim3 ggrid(D_ / 128, M_ / 128);   // (8, 64)
    gemm_f16<<<ggrid, 256>>>(Q, Wq, bq, nullptr, 0);
    gemm_f16<<<ggrid, 256>>>(K, Wk, bk, nullptr, 1);
    gemm_f16<<<ggrid, 256>>>(V, Wv, bv, nullptr, 2);

    flash_f16<<<dim3(S_ / 256, H_, B_), 256, FSMEM>>>();

    gemm_f16<<<ggrid, 256>>>(nullptr, Wo, bo, out, 3);
}

// round 13
// speedup vs baseline: 1.1813x; 1.1813x over previous
#include <cuda_runtime.h>
#include <cuda_fp16.h>
#include <cstdint>
#include <math.h>

// Problem constants
constexpr int B_  = 4;
constexpr int S_  = 2048;
constexpr int D_  = 1024;
constexpr int H_  = 16;
constexpr int DK_ = 64;
constexpr int M_  = B_ * S_;   // 8192

// Scratch (device globals — no allocation allowed)
__device__ __half g_qh[(size_t)B_ * H_ * S_ * DK_];   // [B,H,S,DK]
__device__ __half g_kh[(size_t)B_ * H_ * S_ * DK_];
__device__ __half g_vh[(size_t)B_ * H_ * S_ * DK_];
__device__ float  g_ctx[(size_t)B_ * S_ * D_];        // [B,S,D] fp32

// ---------------------------------------------------------------------------
// helpers (all non-suffixed PTX: works under generic sm_103 target)
// ---------------------------------------------------------------------------
__device__ __forceinline__ uint32_t f2tf32(float f) {
    uint32_t r;
    asm("cvt.rna.tf32.f32 %0, %1;" : "=r"(r) : "f"(f));
    return r;
}

__device__ __forceinline__ void mma_tf32_16n8k8(float* c, const uint32_t* a,
                                                uint32_t b0, uint32_t b1) {
    asm volatile(
        "mma.sync.aligned.m16n8k8.row.col.f32.tf32.tf32.f32 "
        "{%0,%1,%2,%3}, {%4,%5,%6,%7}, {%8,%9}, {%0,%1,%2,%3};"
        : "+f"(c[0]), "+f"(c[1]), "+f"(c[2]), "+f"(c[3])
        : "r"(a[0]), "r"(a[1]), "r"(a[2]), "r"(a[3]), "r"(b0), "r"(b1));
}

__device__ __forceinline__ void mma_f16_16n8k16(float* c, const uint32_t* a,
                                                uint32_t b0, uint32_t b1) {
    asm volatile(
        "mma.sync.aligned.m16n8k16.row.col.f32.f16.f16.f32 "
        "{%0,%1,%2,%3}, {%4,%5,%6,%7}, {%8,%9}, {%0,%1,%2,%3};"
        : "+f"(c[0]), "+f"(c[1]), "+f"(c[2]), "+f"(c[3])
        : "r"(a[0]), "r"(a[1]), "r"(a[2]), "r"(a[3]), "r"(b0), "r"(b1));
}

__device__ __forceinline__ uint32_t smem_u32(const void* p) {
    uint32_t a;
    asm("{ .reg .u64 t; cvta.to.shared.u64 t, %1; cvt.u32.u64 %0, t; }"
        : "=r"(a) : "l"(p));
    return a;
}
__device__ __forceinline__ void cp_async16(uint32_t saddr, const void* g) {
    asm volatile("cp.async.ca.shared.global [%0], [%1], 16;"
                 :: "r"(saddr), "l"(g));
}
#define CP_COMMIT() asm volatile("cp.async.commit_group;" ::: "memory")
#define CP_WAIT0()  asm volatile("cp.async.wait_group 0;" ::: "memory")
#define CP_WAIT1()  asm volatile("cp.async.wait_group 1;" ::: "memory")

__device__ __forceinline__ void ldsm_x4(uint32_t& r0, uint32_t& r1,
                                        uint32_t& r2, uint32_t& r3,
                                        uint32_t addr) {
    asm volatile("ldmatrix.sync.aligned.m8n8.x4.shared.b16 {%0,%1,%2,%3}, [%4];"
                 : "=r"(r0), "=r"(r1), "=r"(r2), "=r"(r3) : "r"(addr));
}
__device__ __forceinline__ void ldsm_x4_trans(uint32_t& r0, uint32_t& r1,
                                              uint32_t& r2, uint32_t& r3,
                                              uint32_t addr) {
    asm volatile("ldmatrix.sync.aligned.m8n8.x4.trans.shared.b16 {%0,%1,%2,%3}, [%4];"
                 : "=r"(r0), "=r"(r1), "=r"(r2), "=r"(r3) : "r"(addr));
}

// ---------------------------------------------------------------------------
// TF32 tensor-core GEMM (EXACT R11 version — proven 147.5us/GEMM).
// Epilogue for which<3 stores fp16 Q/K/V; which==3 reads g_ctx, writes fp32.
// ---------------------------------------------------------------------------
constexpr int BK  = 16;
constexpr int LDA = 20;

__global__ __launch_bounds__(256, 2) void gemm_tf32(
    const float* __restrict__ X, const float* __restrict__ W,
    const float* __restrict__ bias, float* __restrict__ dst, int which)
{
    __shared__ uint32_t As[2][128 * LDA];
    __shared__ uint32_t Bs[2][128 * LDA];

    const int tid = threadIdx.x;
    const int wid = tid >> 5;
    const int lane = tid & 31;
    const int m0 = blockIdx.y * 128;
    const int n0 = blockIdx.x * 128;
    const int warp_m = (wid & 3) * 32;
    const int warp_n = (wid >> 2) * 64;

    const float* Xin = (which == 3) ? (const float*)g_ctx : X;

    const int r0 = tid >> 2;
    const int kq = (tid & 3) * 4;

    const float* gA = Xin + (size_t)m0 * D_;
    const float* gB = W + (size_t)n0 * D_;

    float acc[2][8][4];
#pragma unroll
    for (int i = 0; i < 2; i++)
#pragma unroll
        for (int j = 0; j < 8; j++)
#pragma unroll
            for (int r = 0; r < 4; r++) acc[i][j][r] = 0.f;

    float4 pa0, pa1, pb0, pb1;

    auto ldg = [&](int t) {
        const float* a = gA + (size_t)r0 * D_ + t * BK + kq;
        pa0 = *(const float4*)a;
        pa1 = *(const float4*)(a + (size_t)64 * D_);
        const float* b = gB + (size_t)r0 * D_ + t * BK + kq;
        pb0 = *(const float4*)b;
        pb1 = *(const float4*)(b + (size_t)64 * D_);
    };
    auto sts = [&](int s) {
        uint32_t* A = As[s];
        uint32_t* Bsh = Bs[s];
        int o0 = r0 * LDA + kq;
        int o1 = (r0 + 64) * LDA + kq;
        A[o0 + 0] = f2tf32(pa0.x); A[o0 + 1] = f2tf32(pa0.y);
        A[o0 + 2] = f2tf32(pa0.z); A[o0 + 3] = f2tf32(pa0.w);
        A[o1 + 0] = f2tf32(pa1.x); A[o1 + 1] = f2tf32(pa1.y);
        A[o1 + 2] = f2tf32(pa1.z); A[o1 + 3] = f2tf32(pa1.w);
        Bsh[o0 + 0] = f2tf32(pb0.x); Bsh[o0 + 1] = f2tf32(pb0.y);
        Bsh[o0 + 2] = f2tf32(pb0.z); Bsh[o0 + 3] = f2tf32(pb0.w);
        Bsh[o1 + 0] = f2tf32(pb1.x); Bsh[o1 + 1] = f2tf32(pb1.y);
        Bsh[o1 + 2] = f2tf32(pb1.z); Bsh[o1 + 3] = f2tf32(pb1.w);
    };

    ldg(0);
    sts(0);
    __syncthreads();

    const int r8 = lane >> 2;
    const int c4 = lane & 3;

    for (int t = 0; t < D_ / BK; t++) {
        int s = t & 1;
        if (t < D_ / BK - 1) ldg(t + 1);

#pragma unroll
        for (int ks = 0; ks < 2; ks++) {
            const int kk = ks * 8;
            uint32_t a[2][4], b[8][2];
#pragma unroll
            for (int im = 0; im < 2; im++) {
                int mr = warp_m + 16 * im + r8;
                a[im][0] = As[s][mr * LDA + kk + c4];
                a[im][1] = As[s][(mr + 8) * LDA + kk + c4];
                a[im][2] = As[s][mr * LDA + kk + c4 + 4];
                a[im][3] = As[s][(mr + 8) * LDA + kk + c4 + 4];
            }
#pragma unroll
            for (int jn = 0; jn < 8; jn++) {
                int nr = warp_n + 8 * jn + r8;
                b[jn][0] = Bs[s][nr * LDA + kk + c4];
                b[jn][1] = Bs[s][nr * LDA + kk + c4 + 4];
            }
#pragma unroll
            for (int im = 0; im < 2; im++)
#pragma unroll
                for (int jn = 0; jn < 8; jn++)
                    mma_tf32_16n8k8(acc[im][jn], a[im], b[jn][0], b[jn][1]);
        }

        if (t < D_ / BK - 1) sts(s ^ 1);
        __syncthreads();
    }

    const int c2 = (lane & 3) * 2;
#pragma unroll
    for (int im = 0; im < 2; im++) {
#pragma unroll
        for (int jn = 0; jn < 8; jn++) {
            int n = n0 + warp_n + 8 * jn + c2;
            float bx = bias[n], by = bias[n + 1];
            int mA = m0 + warp_m + 16 * im + r8;
            int mB = mA + 8;
            float2 v0 = make_float2(acc[im][jn][0] + bx, acc[im][jn][1] + by);
            float2 v1 = make_float2(acc[im][jn][2] + bx, acc[im][jn][3] + by);
            if (which < 3) {
                __half* outh = (which == 0) ? g_qh : (which == 1) ? g_kh : g_vh;
                __half2 h0 = __floats2half2_rn(v0.x, v0.y);
                __half2 h1 = __floats2half2_rn(v1.x, v1.y);
                int h = n >> 6, dk = n & 63;
                int bA = mA >> 11, sA = mA & (S_ - 1);
                int bB = mB >> 11, sB = mB & (S_ - 1);
                *(__half2*)&outh[(((size_t)(bA * H_ + h) * S_ + sA) << 6) + dk] = h0;
                *(__half2*)&outh[(((size_t)(bB * H_ + h) * S_ + sB) << 6) + dk] = h1;
            } else {
                *(float2*)&dst[(size_t)mA * D_ + n] = v0;
                *(float2*)&dst[(size_t)mB * D_ + n] = v1;
            }
        }
    }
}

// ---------------------------------------------------------------------------
// Flash attention v7: fp16 m16n8k16, P KEPT IN REGISTERS (S-accumulator
// fragment layout == PV A-fragment layout; no P smem, no P ldsm, no
// syncwarps). Q/K via ldsm, V via ldsm.trans, cp.async 2-stage K/V.
// Same values reach every MMA as v6 -> rel_err bitwise unchanged.
// ---------------------------------------------------------------------------
constexpr int QBYTES = 256 * 144;
constexpr int KSTAGE = 64 * 144;
constexpr int VSTAGE = 64 * 144;
constexpr int FSMEM  = QBYTES + 2 * KSTAGE + 2 * VSTAGE;  // 73728

__global__ __launch_bounds__(256, 1) void flash_f16()
{
    extern __shared__ char smc[];
    char* sQ = smc;
    char* sK = sQ + QBYTES;
    char* sV = sK + 2 * KSTAGE;

    const uint32_t sqb = smem_u32(sQ);
    const uint32_t skb = smem_u32(sK);
    const uint32_t svb = smem_u32(sV);

    const int tid = threadIdx.x;
    const int wid = tid >> 5;
    const int lane = tid & 31;
    const int r8 = lane >> 2;
    const int c4 = lane & 3;
    const int lm = lane >> 3;
    const int lr7 = lane & 7;

    const uint32_t laneA =
        (uint32_t)(((lm & 1) * 8 + lr7) * 144 + (lm >> 1) * 16);
    const uint32_t laneB =
        (uint32_t)(((lm >> 1) * 8 + lr7) * 144 + (lm & 1) * 16);
    const uint32_t laneV =
        (uint32_t)(((lm & 1) * 8 + lr7) * 144 + (lm >> 1) * 16);

    const int q0 = blockIdx.x * 256;
    const int h = blockIdx.y;
    const int b = blockIdx.z;
    const size_t base = (size_t)(b * H_ + h) * S_ * DK_;
    const __half* qg = g_qh + base + (size_t)q0 * DK_;
    const __half* kg = g_kh + base;
    const __half* vg = g_vh + base;

    const int wr = wid * 32;

    auto issue_chunk = [&](int kb, int st) {
#pragma unroll
        for (int i = 0; i < 2; i++) {
            int idx = tid + i * 256;
            int row = idx >> 3;
            int c16 = (idx & 7) * 16;
            cp_async16(skb + (uint32_t)(st * KSTAGE + row * 144) + c16,
                       kg + (size_t)(kb + row) * DK_ + (idx & 7) * 8);
            cp_async16(svb + (uint32_t)(st * VSTAGE + row * 144) + c16,
                       vg + (size_t)(kb + row) * DK_ + (idx & 7) * 8);
        }
        CP_COMMIT();
    };

#pragma unroll
    for (int i = 0; i < 8; i++) {
        int idx = tid + i * 256;
        int row = idx >> 3;
        int c16 = (idx & 7) * 16;
        cp_async16(sqb + (uint32_t)(row * 144) + c16,
                   qg + (size_t)row * DK_ + (idx & 7) * 8);
    }
    CP_COMMIT();
    issue_chunk(0, 0);

    CP_WAIT1();
    __syncthreads();

    uint32_t aq[2][4][4];
    {
        const __half2 hs = __half2half2(__float2half_rn(0.125f));
#pragma unroll
        for (int t = 0; t < 2; t++) {
#pragma unroll
            for (int kc = 0; kc < 4; kc++) {
                uint32_t addr = sqb + (uint32_t)((wr + 16 * t) * 144 + kc * 32) + laneA;
                ldsm_x4(aq[t][kc][0], aq[t][kc][1], aq[t][kc][2], aq[t][kc][3], addr);
#pragma unroll
                for (int r = 0; r < 4; r++) {
                    __half2 v = *(__half2*)&aq[t][kc][r];
                    v = __hmul2(v, hs);
                    aq[t][kc][r] = *(uint32_t*)&v;
                }
            }
        }
    }

    float mrow[2][2], lrow[2][2];
    float o0[8][4], o1[8][4];
#pragma unroll
    for (int t = 0; t < 2; t++) {
        mrow[t][0] = mrow[t][1] = -1e30f;
        lrow[t][0] = lrow[t][1] = 0.f;
    }
#pragma unroll
    for (int j = 0; j < 8; j++)
#pragma unroll
        for (int r = 0; r < 4; r++) { o0[j][r] = 0.f; o1[j][r] = 0.f; }

    for (int c = 0; c < S_ / 64; c++) {
        const int st = c & 1;
        CP_WAIT0();
        __syncthreads();
        if (c + 1 < S_ / 64) issue_chunk((c + 1) * 64, st ^ 1);

        const uint32_t skc = skb + (uint32_t)(st * KSTAGE) + laneB;
        const uint32_t svc = svb + (uint32_t)(st * VSTAGE) + laneV;

        // ---- S = Q K^T ----
        float s0[8][4], s1[8][4];
#pragma unroll
        for (int j = 0; j < 8; j++)
#pragma unroll
            for (int r = 0; r < 4; r++) { s0[j][r] = 0.f; s1[j][r] = 0.f; }

#pragma unroll
        for (int kc = 0; kc < 4; kc++) {
#pragma unroll
            for (int jnp = 0; jnp < 4; jnp++) {
                uint32_t k0, k1, k2, k3;
                ldsm_x4(k0, k1, k2, k3,
                        skc + (uint32_t)(jnp * 16 * 144 + kc * 32));
                mma_f16_16n8k16(s0[2 * jnp], aq[0][kc], k0, k1);
                mma_f16_16n8k16(s1[2 * jnp], aq[1][kc], k0, k1);
                mma_f16_16n8k16(s0[2 * jnp + 1], aq[0][kc], k2, k3);
                mma_f16_16n8k16(s1[2 * jnp + 1], aq[1][kc], k2, k3);
            }
        }

        // ---- online softmax; pack P directly into A-fragments ----
        uint32_t ph0[8][2], ph1[8][2];   // [jn][{rows r8 / r8+8}]
#pragma unroll
        for (int t = 0; t < 2; t++) {
            float (*s)[4] = (t == 0) ? s0 : s1;
            float (*o)[4] = (t == 0) ? o0 : o1;
            uint32_t (*ph)[2] = (t == 0) ? ph0 : ph1;
            float mx0 = -1e30f, mx1 = -1e30f;
#pragma unroll
            for (int jn = 0; jn < 8; jn++) {
                mx0 = fmaxf(mx0, fmaxf(s[jn][0], s[jn][1]));
                mx1 = fmaxf(mx1, fmaxf(s[jn][2], s[jn][3]));
            }
            mx0 = fmaxf(mx0, __shfl_xor_sync(0xffffffffu, mx0, 1));
            mx0 = fmaxf(mx0, __shfl_xor_sync(0xffffffffu, mx0, 2));
            mx1 = fmaxf(mx1, __shfl_xor_sync(0xffffffffu, mx1, 1));
            mx1 = fmaxf(mx1, __shfl_xor_sync(0xffffffffu, mx1, 2));
            float mn0 = fmaxf(mrow[t][0], mx0), mn1 = fmaxf(mrow[t][1], mx1);
            float alpha0 = __expf(mrow[t][0] - mn0);
            float alpha1 = __expf(mrow[t][1] - mn1);
            float sum0 = 0.f, sum1 = 0.f;
#pragma unroll
            for (int jn = 0; jn < 8; jn++) {
                float e0 = __expf(s[jn][0] - mn0);
                float e1 = __expf(s[jn][1] - mn0);
                float e2 = __expf(s[jn][2] - mn1);
                float e3 = __expf(s[jn][3] - mn1);
                sum0 += e0 + e1;
                sum1 += e2 + e3;
                __half2 hA = __floats2half2_rn(e0, e1);
                __half2 hB = __floats2half2_rn(e2, e3);
                ph[jn][0] = *(uint32_t*)&hA;
                ph[jn][1] = *(uint32_t*)&hB;
            }
            sum0 += __shfl_xor_sync(0xffffffffu, sum0, 1);
            sum0 += __shfl_xor_sync(0xffffffffu, sum0, 2);
            sum1 += __shfl_xor_sync(0xffffffffu, sum1, 1);
            sum1 += __shfl_xor_sync(0xffffffffu, sum1, 2);
            lrow[t][0] = lrow[t][0] * alpha0 + sum0;
            lrow[t][1] = lrow[t][1] * alpha1 + sum1;
            mrow[t][0] = mn0;
            mrow[t][1] = mn1;
#pragma unroll
            for (int jn = 0; jn < 8; jn++) {
                o[jn][0] *= alpha0; o[jn][1] *= alpha0;
                o[jn][2] *= alpha1; o[jn][3] *= alpha1;
            }
        }

        // ---- O += P V : A-frags straight from registers ----
#pragma unroll
        for (int kc = 0; kc < 4; kc++) {
            uint32_t ap0[4] = { ph0[2 * kc][0], ph0[2 * kc][1],
                                ph0[2 * kc + 1][0], ph0[2 * kc + 1][1] };
            uint32_t ap1[4] = { ph1[2 * kc][0], ph1[2 * kc][1],
                                ph1[2 * kc + 1][0], ph1[2 * kc + 1][1] };
#pragma unroll
            for (int jnp = 0; jnp < 4; jnp++) {
                uint32_t v0, v1, v2, v3;
                ldsm_x4_trans(v0, v1, v2, v3,
                              svc + (uint32_t)(kc * 16 * 144 + jnp * 32));
                mma_f16_16n8k16(o0[2 * jnp], ap0, v0, v1);
                mma_f16_16n8k16(o1[2 * jnp], ap1, v0, v1);
                mma_f16_16n8k16(o0[2 * jnp + 1], ap0, v2, v3);
                mma_f16_16n8k16(o1[2 * jnp + 1], ap1, v2, v3);
            }
        }
    }

    // ---- epilogue: normalize + write ctx [B,S,D] fp32 ----
#pragma unroll
    for (int t = 0; t < 2; t++) {
        float (*o)[4] = (t == 0) ? o0 : o1;
        float inv0 = 1.0f / lrow[t][0], inv1 = 1.0f / lrow[t][1];
        int row0 = q0 + wr + 16 * t + r8;
        int row1 = row0 + 8;
        size_t g0 = ((size_t)b * S_ + row0) * D_ + h * DK_;
        size_t g1 = ((size_t)b * S_ + row1) * D_ + h * DK_;
#pragma unroll
        for (int jn = 0; jn < 8; jn++) {
            int col = 8 * jn + 2 * c4;
            *(float2*)&g_ctx[g0 + col] = make_float2(o[jn][0] * inv0, o[jn][1] * inv0);
            *(float2*)&g_ctx[g1 + col] = make_float2(o[jn][2] * inv1, o[jn][3] * inv1);
        }
    }
}

// ---------------------------------------------------------------------------
// Launch
// ---------------------------------------------------------------------------
extern "C" void kernel_launch(void* const* d_in, const int* in_sizes, int n_in,
                              void* d_out, int out_size)
{
    const float* Q  = (const float*)d_in[0];
    const float* K  = (const float*)d_in[1];
    const float* V  = (const float*)d_in[2];
    const float* Wq = (const float*)d_in[3];
    const float* bq = (const float*)d_in[4];
    const float* Wk = (const float*)d_in[5];
    const float* bk = (const float*)d_in[6];
    const float* Wv = (const float*)d_in[7];
    const float* bv = (const float*)d_in[8];
    const float* Wo = (const float*)d_in[9];
    const float* bo = (const float*)d_in[10];
    float* out = (float*)d_out;

    cudaFuncSetAttribute(flash_f16,
                         cudaFuncAttributeMaxDynamicSharedMemorySize, FSMEM);

    dim3 ggrid(D_ / 128, M_ / 128);   // (8, 64)
    gemm_tf32<<<ggrid, 256>>>(Q, Wq, bq, nullptr, 0);
    gemm_tf32<<<ggrid, 256>>>(K, Wk, bk, nullptr, 1);
    gemm_tf32<<<ggrid, 256>>>(V, Wv, bv, nullptr, 2);

    flash_f16<<<dim3(S_ / 256, H_, B_), 256, FSMEM>>>();

    gemm_tf32<<<ggrid, 256>>>(nullptr, Wo, bo, out, 3);
}

// round 14
// speedup vs baseline: 1.5889x; 1.3450x over previous
#include <cuda_runtime.h>
#include <cuda_fp16.h>
#include <cstdint>
#include <math.h>

// Problem constants
constexpr int B_  = 4;
constexpr int S_  = 2048;
constexpr int D_  = 1024;
constexpr int H_  = 16;
constexpr int DK_ = 64;
constexpr int M_  = B_ * S_;   // 8192

// Scratch (device globals — no allocation allowed)
__device__ __half g_qh[(size_t)B_ * H_ * S_ * DK_];   // [B,H,S,DK]
__device__ __half g_kh[(size_t)B_ * H_ * S_ * DK_];
__device__ __half g_vh[(size_t)B_ * H_ * S_ * DK_];
__device__ float  g_ctx[(size_t)B_ * S_ * D_];        // [B,S,D] fp32

// ---------------------------------------------------------------------------
// helpers (all non-suffixed PTX: works under generic sm_103 target)
// ---------------------------------------------------------------------------
__device__ __forceinline__ void mma_f16_16n8k16(float* c, const uint32_t* a,
                                                uint32_t b0, uint32_t b1) {
    asm volatile(
        "mma.sync.aligned.m16n8k16.row.col.f32.f16.f16.f32 "
        "{%0,%1,%2,%3}, {%4,%5,%6,%7}, {%8,%9}, {%0,%1,%2,%3};"
        : "+f"(c[0]), "+f"(c[1]), "+f"(c[2]), "+f"(c[3])
        : "r"(a[0]), "r"(a[1]), "r"(a[2]), "r"(a[3]), "r"(b0), "r"(b1));
}

__device__ __forceinline__ uint32_t smem_u32(const void* p) {
    uint32_t a;
    asm("{ .reg .u64 t; cvta.to.shared.u64 t, %1; cvt.u32.u64 %0, t; }"
        : "=r"(a) : "l"(p));
    return a;
}
__device__ __forceinline__ void cp_async16(uint32_t saddr, const void* g) {
    asm volatile("cp.async.ca.shared.global [%0], [%1], 16;"
                 :: "r"(saddr), "l"(g));
}
#define CP_COMMIT() asm volatile("cp.async.commit_group;" ::: "memory")
#define CP_WAIT0()  asm volatile("cp.async.wait_group 0;" ::: "memory")
#define CP_WAIT1()  asm volatile("cp.async.wait_group 1;" ::: "memory")

__device__ __forceinline__ void ldsm_x4(uint32_t& r0, uint32_t& r1,
                                        uint32_t& r2, uint32_t& r3,
                                        uint32_t addr) {
    asm volatile("ldmatrix.sync.aligned.m8n8.x4.shared.b16 {%0,%1,%2,%3}, [%4];"
                 : "=r"(r0), "=r"(r1), "=r"(r2), "=r"(r3) : "r"(addr));
}
__device__ __forceinline__ void ldsm_x4_trans(uint32_t& r0, uint32_t& r1,
                                              uint32_t& r2, uint32_t& r3,
                                              uint32_t addr) {
    asm volatile("ldmatrix.sync.aligned.m8n8.x4.trans.shared.b16 {%0,%1,%2,%3}, [%4];"
                 : "=r"(r0), "=r"(r1), "=r"(r2), "=r"(r3) : "r"(addr));
}

// ---------------------------------------------------------------------------
// FP16 tensor-core GEMM v2: Y[M,N] = X @ W^T + bias (fp32 in, fp32 acc).
// BM=BN=128, BK=16, 256 threads, 8 warps (4x2), warp tile 32x64.
// Smem: [128 rows][32B] per tensor per stage, XOR-16B swizzle
// (chunk ^= (row>>2)&1). Verified: coalesced LDG (4 lanes/row, 64B/row),
// conflict-free STS.64 (each half-warp phase = all 32 banks once),
// conflict-free ldsm (each 8-lane phase = 8 distinct quads).
// Fragments: 2 A-ldsm.x4 + 4 B-ldsm.x4 + 16 HMMA.16816 per warp-iter.
// which: 0/1/2 -> fp16 split-head out; 3 -> read g_ctx, fp32 dst.
// ---------------------------------------------------------------------------
constexpr int HROW = 16;   // halves per smem row (32 B, no padding; swizzled)

__global__ __launch_bounds__(256, 2) void gemm_f16(
    const float* __restrict__ X, const float* __restrict__ W,
    const float* __restrict__ bias, float* __restrict__ dst, int which)
{
    __shared__ __half As[2][128 * HROW];
    __shared__ __half Bs[2][128 * HROW];

    const int tid = threadIdx.x;
    const int wid = tid >> 5;
    const int lane = tid & 31;
    const int m0 = blockIdx.y * 128;
    const int n0 = blockIdx.x * 128;
    const int warp_m = (wid & 3) * 32;
    const int warp_n = (wid >> 2) * 64;

    const float* Xin = (which == 3) ? (const float*)g_ctx : X;

    // ---- fill mapping: 4 lanes per row, rows r0 and r0+64, float4 each ----
    const int r0 = tid >> 2;          // 0..63
    const int q  = tid & 3;           // 0..3 (16B chunk of the 64B row-piece)

    const float* gA = Xin + (size_t)(m0 + r0) * D_ + q * 4;
    const float* gB = W + (size_t)(n0 + r0) * D_ + q * 4;

    // STS.64 half-index: row*16 + (chunk^sw)*8 + (q&1)*4, chunk=q>>1,
    // sw=(row>>2)&1 (same for r0 and r0+64 since 64/4 is even).
    const int swf = (r0 >> 2) & 1;
    const int sidx0 = r0 * HROW + ((q >> 1) ^ swf) * 8 + (q & 1) * 4;
    const int sidx1 = sidx0 + 64 * HROW;

    float acc[2][8][4];
#pragma unroll
    for (int i = 0; i < 2; i++)
#pragma unroll
        for (int j = 0; j < 8; j++)
#pragma unroll
            for (int r = 0; r < 4; r++) acc[i][j][r] = 0.f;

    float4 pa0, pa1, pb0, pb1;

    auto ldg = [&](int t) {
        pa0 = *(const float4*)(gA + t * 16);
        pa1 = *(const float4*)(gA + t * 16 + (size_t)64 * D_);
        pb0 = *(const float4*)(gB + t * 16);
        pb1 = *(const float4*)(gB + t * 16 + (size_t)64 * D_);
    };
    auto sts = [&](int s) {
        __half2 h0 = __floats2half2_rn(pa0.x, pa0.y);
        __half2 h1 = __floats2half2_rn(pa0.z, pa0.w);
        uint2 u;
        u.x = *(uint32_t*)&h0; u.y = *(uint32_t*)&h1;
        *(uint2*)&As[s][sidx0] = u;
        h0 = __floats2half2_rn(pa1.x, pa1.y);
        h1 = __floats2half2_rn(pa1.z, pa1.w);
        u.x = *(uint32_t*)&h0; u.y = *(uint32_t*)&h1;
        *(uint2*)&As[s][sidx1] = u;
        h0 = __floats2half2_rn(pb0.x, pb0.y);
        h1 = __floats2half2_rn(pb0.z, pb0.w);
        u.x = *(uint32_t*)&h0; u.y = *(uint32_t*)&h1;
        *(uint2*)&Bs[s][sidx0] = u;
        h0 = __floats2half2_rn(pb1.x, pb1.y);
        h1 = __floats2half2_rn(pb1.z, pb1.w);
        u.x = *(uint32_t*)&h0; u.y = *(uint32_t*)&h1;
        *(uint2*)&Bs[s][sidx1] = u;
    };

    ldg(0);
    sts(0);
    __syncthreads();

    // ---- ldsm fragment addresses (lane-constant; swizzle bit folded in) ----
    const int lm = lane >> 3;
    const int lr7 = lane & 7;
    // A x4: m0: rows0-7 k0; m1: rows8-15 k0; m2: rows0-7 k8; m3: rows8-15 k8
    const int rA = (lm & 1) * 8 + lr7;
    const int cA = lm >> 1;
    // B x4: m0: cols0-7 k0; m1: cols0-7 k8; m2: cols8-15 k0; m3: cols8-15 k8
    const int rB = (lm >> 1) * 8 + lr7;
    const int cB = lm & 1;

    uint32_t aAddr[2][2], bAddr[2][4];   // [stage][tile]
    const uint32_t sa0 = smem_u32(&As[0][0]);
    const uint32_t sb0 = smem_u32(&Bs[0][0]);
    const uint32_t stageA = (uint32_t)(128 * HROW * 2);   // bytes per stage
#pragma unroll
    for (int t = 0; t < 2; t++) {
        int row = warp_m + 16 * t + rA;
        uint32_t byte = (uint32_t)(row * 32 + ((cA ^ ((row >> 2) & 1)) * 16));
        aAddr[0][t] = sa0 + byte;
        aAddr[1][t] = sa0 + stageA + byte;
    }
#pragma unroll
    for (int jnp = 0; jnp < 4; jnp++) {
        int row = warp_n + 16 * jnp + rB;
        uint32_t byte = (uint32_t)(row * 32 + ((cB ^ ((row >> 2) & 1)) * 16));
        bAddr[0][jnp] = sb0 + byte;
        bAddr[1][jnp] = sb0 + stageA + byte;
    }

    for (int t = 0; t < D_ / 16; t++) {
        int s = t & 1;
        if (t < D_ / 16 - 1) ldg(t + 1);

        uint32_t a[2][4];
        ldsm_x4(a[0][0], a[0][1], a[0][2], a[0][3], aAddr[s][0]);
        ldsm_x4(a[1][0], a[1][1], a[1][2], a[1][3], aAddr[s][1]);
#pragma unroll
        for (int jnp = 0; jnp < 4; jnp++) {
            uint32_t b0, b1, b2, b3;
            ldsm_x4(b0, b1, b2, b3, bAddr[s][jnp]);
            mma_f16_16n8k16(acc[0][2 * jnp], a[0], b0, b1);
            mma_f16_16n8k16(acc[1][2 * jnp], a[1], b0, b1);
            mma_f16_16n8k16(acc[0][2 * jnp + 1], a[0], b2, b3);
            mma_f16_16n8k16(acc[1][2 * jnp + 1], a[1], b2, b3);
        }

        if (t < D_ / 16 - 1) sts(s ^ 1);
        __syncthreads();
    }

    const int r8 = lane >> 2;
    const int c2 = (lane & 3) * 2;
#pragma unroll
    for (int im = 0; im < 2; im++) {
#pragma unroll
        for (int jn = 0; jn < 8; jn++) {
            int n = n0 + warp_n + 8 * jn + c2;
            float bx = bias[n], by = bias[n + 1];
            int mA = m0 + warp_m + 16 * im + r8;
            int mB = mA + 8;
            float2 v0 = make_float2(acc[im][jn][0] + bx, acc[im][jn][1] + by);
            float2 v1 = make_float2(acc[im][jn][2] + bx, acc[im][jn][3] + by);
            if (which < 3) {
                __half* outh = (which == 0) ? g_qh : (which == 1) ? g_kh : g_vh;
                __half2 h0 = __floats2half2_rn(v0.x, v0.y);
                __half2 h1 = __floats2half2_rn(v1.x, v1.y);
                int h = n >> 6, dk = n & 63;
                int bA = mA >> 11, sA = mA & (S_ - 1);
                int bB = mB >> 11, sB = mB & (S_ - 1);
                *(__half2*)&outh[(((size_t)(bA * H_ + h) * S_ + sA) << 6) + dk] = h0;
                *(__half2*)&outh[(((size_t)(bB * H_ + h) * S_ + sB) << 6) + dk] = h1;
            } else {
                *(float2*)&dst[(size_t)mA * D_ + n] = v0;
                *(float2*)&dst[(size_t)mB * D_ + n] = v1;
            }
        }
    }
}

// ---------------------------------------------------------------------------
// Flash attention v7 (fp16 m16n8k16, P-in-registers) — UNCHANGED from R13
// (proven 241us, rel_err component validated).
// ---------------------------------------------------------------------------
constexpr int QBYTES = 256 * 144;
constexpr int KSTAGE = 64 * 144;
constexpr int VSTAGE = 64 * 144;
constexpr int FSMEM  = QBYTES + 2 * KSTAGE + 2 * VSTAGE;  // 73728

__global__ __launch_bounds__(256, 1) void flash_f16()
{
    extern __shared__ char smc[];
    char* sQ = smc;
    char* sK = sQ + QBYTES;
    char* sV = sK + 2 * KSTAGE;

    const uint32_t sqb = smem_u32(sQ);
    const uint32_t skb = smem_u32(sK);
    const uint32_t svb = smem_u32(sV);

    const int tid = threadIdx.x;
    const int wid = tid >> 5;
    const int lane = tid & 31;
    const int r8 = lane >> 2;
    const int c4 = lane & 3;
    const int lm = lane >> 3;
    const int lr7 = lane & 7;

    const uint32_t laneA =
        (uint32_t)(((lm & 1) * 8 + lr7) * 144 + (lm >> 1) * 16);
    const uint32_t laneB =
        (uint32_t)(((lm >> 1) * 8 + lr7) * 144 + (lm & 1) * 16);
    const uint32_t laneV =
        (uint32_t)(((lm & 1) * 8 + lr7) * 144 + (lm >> 1) * 16);

    const int q0 = blockIdx.x * 256;
    const int h = blockIdx.y;
    const int b = blockIdx.z;
    const size_t base = (size_t)(b * H_ + h) * S_ * DK_;
    const __half* qg = g_qh + base + (size_t)q0 * DK_;
    const __half* kg = g_kh + base;
    const __half* vg = g_vh + base;

    const int wr = wid * 32;

    auto issue_chunk = [&](int kb, int st) {
#pragma unroll
        for (int i = 0; i < 2; i++) {
            int idx = tid + i * 256;
            int row = idx >> 3;
            int c16 = (idx & 7) * 16;
            cp_async16(skb + (uint32_t)(st * KSTAGE + row * 144) + c16,
                       kg + (size_t)(kb + row) * DK_ + (idx & 7) * 8);
            cp_async16(svb + (uint32_t)(st * VSTAGE + row * 144) + c16,
                       vg + (size_t)(kb + row) * DK_ + (idx & 7) * 8);
        }
        CP_COMMIT();
    };

#pragma unroll
    for (int i = 0; i < 8; i++) {
        int idx = tid + i * 256;
        int row = idx >> 3;
        int c16 = (idx & 7) * 16;
        cp_async16(sqb + (uint32_t)(row * 144) + c16,
                   qg + (size_t)row * DK_ + (idx & 7) * 8);
    }
    CP_COMMIT();
    issue_chunk(0, 0);

    CP_WAIT1();
    __syncthreads();

    uint32_t aq[2][4][4];
    {
        const __half2 hs = __half2half2(__float2half_rn(0.125f));
#pragma unroll
        for (int t = 0; t < 2; t++) {
#pragma unroll
            for (int kc = 0; kc < 4; kc++) {
                uint32_t addr = sqb + (uint32_t)((wr + 16 * t) * 144 + kc * 32) + laneA;
                ldsm_x4(aq[t][kc][0], aq[t][kc][1], aq[t][kc][2], aq[t][kc][3], addr);
#pragma unroll
                for (int r = 0; r < 4; r++) {
                    __half2 v = *(__half2*)&aq[t][kc][r];
                    v = __hmul2(v, hs);
                    aq[t][kc][r] = *(uint32_t*)&v;
                }
            }
        }
    }

    float mrow[2][2], lrow[2][2];
    float o0[8][4], o1[8][4];
#pragma unroll
    for (int t = 0; t < 2; t++) {
        mrow[t][0] = mrow[t][1] = -1e30f;
        lrow[t][0] = lrow[t][1] = 0.f;
    }
#pragma unroll
    for (int j = 0; j < 8; j++)
#pragma unroll
        for (int r = 0; r < 4; r++) { o0[j][r] = 0.f; o1[j][r] = 0.f; }

    for (int c = 0; c < S_ / 64; c++) {
        const int st = c & 1;
        CP_WAIT0();
        __syncthreads();
        if (c + 1 < S_ / 64) issue_chunk((c + 1) * 64, st ^ 1);

        const uint32_t skc = skb + (uint32_t)(st * KSTAGE) + laneB;
        const uint32_t svc = svb + (uint32_t)(st * VSTAGE) + laneV;

        float s0[8][4], s1[8][4];
#pragma unroll
        for (int j = 0; j < 8; j++)
#pragma unroll
            for (int r = 0; r < 4; r++) { s0[j][r] = 0.f; s1[j][r] = 0.f; }

#pragma unroll
        for (int kc = 0; kc < 4; kc++) {
#pragma unroll
            for (int jnp = 0; jnp < 4; jnp++) {
                uint32_t k0, k1, k2, k3;
                ldsm_x4(k0, k1, k2, k3,
                        skc + (uint32_t)(jnp * 16 * 144 + kc * 32));
                mma_f16_16n8k16(s0[2 * jnp], aq[0][kc], k0, k1);
                mma_f16_16n8k16(s1[2 * jnp], aq[1][kc], k0, k1);
                mma_f16_16n8k16(s0[2 * jnp + 1], aq[0][kc], k2, k3);
                mma_f16_16n8k16(s1[2 * jnp + 1], aq[1][kc], k2, k3);
            }
        }

        uint32_t ph0[8][2], ph1[8][2];
#pragma unroll
        for (int t = 0; t < 2; t++) {
            float (*s)[4] = (t == 0) ? s0 : s1;
            float (*o)[4] = (t == 0) ? o0 : o1;
            uint32_t (*ph)[2] = (t == 0) ? ph0 : ph1;
            float mx0 = -1e30f, mx1 = -1e30f;
#pragma unroll
            for (int jn = 0; jn < 8; jn++) {
                mx0 = fmaxf(mx0, fmaxf(s[jn][0], s[jn][1]));
                mx1 = fmaxf(mx1, fmaxf(s[jn][2], s[jn][3]));
            }
            mx0 = fmaxf(mx0, __shfl_xor_sync(0xffffffffu, mx0, 1));
            mx0 = fmaxf(mx0, __shfl_xor_sync(0xffffffffu, mx0, 2));
            mx1 = fmaxf(mx1, __shfl_xor_sync(0xffffffffu, mx1, 1));
            mx1 = fmaxf(mx1, __shfl_xor_sync(0xffffffffu, mx1, 2));
            float mn0 = fmaxf(mrow[t][0], mx0), mn1 = fmaxf(mrow[t][1], mx1);
            float alpha0 = __expf(mrow[t][0] - mn0);
            float alpha1 = __expf(mrow[t][1] - mn1);
            float sum0 = 0.f, sum1 = 0.f;
#pragma unroll
            for (int jn = 0; jn < 8; jn++) {
                float e0 = __expf(s[jn][0] - mn0);
                float e1 = __expf(s[jn][1] - mn0);
                float e2 = __expf(s[jn][2] - mn1);
                float e3 = __expf(s[jn][3] - mn1);
                sum0 += e0 + e1;
                sum1 += e2 + e3;
                __half2 hA = __floats2half2_rn(e0, e1);
                __half2 hB = __floats2half2_rn(e2, e3);
                ph[jn][0] = *(uint32_t*)&hA;
                ph[jn][1] = *(uint32_t*)&hB;
            }
            sum0 += __shfl_xor_sync(0xffffffffu, sum0, 1);
            sum0 += __shfl_xor_sync(0xffffffffu, sum0, 2);
            sum1 += __shfl_xor_sync(0xffffffffu, sum1, 1);
            sum1 += __shfl_xor_sync(0xffffffffu, sum1, 2);
            lrow[t][0] = lrow[t][0] * alpha0 + sum0;
            lrow[t][1] = lrow[t][1] * alpha1 + sum1;
            mrow[t][0] = mn0;
            mrow[t][1] = mn1;
#pragma unroll
            for (int jn = 0; jn < 8; jn++) {
                o[jn][0] *= alpha0; o[jn][1] *= alpha0;
                o[jn][2] *= alpha1; o[jn][3] *= alpha1;
            }
        }

#pragma unroll
        for (int kc = 0; kc < 4; kc++) {
            uint32_t ap0[4] = { ph0[2 * kc][0], ph0[2 * kc][1],
                                ph0[2 * kc + 1][0], ph0[2 * kc + 1][1] };
            uint32_t ap1[4] = { ph1[2 * kc][0], ph1[2 * kc][1],
                                ph1[2 * kc + 1][0], ph1[2 * kc + 1][1] };
#pragma unroll
            for (int jnp = 0; jnp < 4; jnp++) {
                uint32_t v0, v1, v2, v3;
                ldsm_x4_trans(v0, v1, v2, v3,
                              svc + (uint32_t)(kc * 16 * 144 + jnp * 32));
                mma_f16_16n8k16(o0[2 * jnp], ap0, v0, v1);
                mma_f16_16n8k16(o1[2 * jnp], ap1, v0, v1);
                mma_f16_16n8k16(o0[2 * jnp + 1], ap0, v2, v3);
                mma_f16_16n8k16(o1[2 * jnp + 1], ap1, v2, v3);
            }
        }
    }

#pragma unroll
    for (int t = 0; t < 2; t++) {
        float (*o)[4] = (t == 0) ? o0 : o1;
        float inv0 = 1.0f / lrow[t][0], inv1 = 1.0f / lrow[t][1];
        int row0 = q0 + wr + 16 * t + r8;
        int row1 = row0 + 8;
        size_t g0 = ((size_t)b * S_ + row0) * D_ + h * DK_;
        size_t g1 = ((size_t)b * S_ + row1) * D_ + h * DK_;
#pragma unroll
        for (int jn = 0; jn < 8; jn++) {
            int col = 8 * jn + 2 * c4;
            *(float2*)&g_ctx[g0 + col] = make_float2(o[jn][0] * inv0, o[jn][1] * inv0);
            *(float2*)&g_ctx[g1 + col] = make_float2(o[jn][2] * inv1, o[jn][3] * inv1);
        }
    }
}

// ---------------------------------------------------------------------------
// Launch
// ---------------------------------------------------------------------------
extern "C" void kernel_launch(void* const* d_in, const int* in_sizes, int n_in,
                              void* d_out, int out_size)
{
    const float* Q  = (const float*)d_in[0];
    const float* K  = (const float*)d_in[1];
    const float* V  = (const float*)d_in[2];
    const float* Wq = (const float*)d_in[3];
    const float* bq = (const float*)d_in[4];
    const float* Wk = (const float*)d_in[5];
    const float* bk = (const float*)d_in[6];
    const float* Wv = (const float*)d_in[7];
    const float* bv = (const float*)d_in[8];
    const float* Wo = (const float*)d_in[9];
    const float* bo = (const float*)d_in[10];
    float* out = (float*)d_out;

    cudaFuncSetAttribute(flash_f16,
                         cudaFuncAttributeMaxDynamicSharedMemorySize, FSMEM);

    dim3 ggrid(D_ / 128, M_ / 128);   // (8, 64)
    gemm_f16<<<ggrid, 256>>>(Q, Wq, bq, nullptr, 0);
    gemm_f16<<<ggrid, 256>>>(K, Wk, bk, nullptr, 1);
    gemm_f16<<<ggrid, 256>>>(V, Wv, bv, nullptr, 2);

    flash_f16<<<dim3(S_ / 256, H_, B_), 256, FSMEM>>>();

    gemm_f16<<<ggrid, 256>>>(nullptr, Wo, bo, out, 3);
}

// round 15
// speedup vs baseline: 1.8095x; 1.1388x over previous
#include <cuda_runtime.h>
#include <cuda_fp16.h>
#include <cstdint>
#include <math.h>

// Problem constants
constexpr int B_  = 4;
constexpr int S_  = 2048;
constexpr int D_  = 1024;
constexpr int H_  = 16;
constexpr int DK_ = 64;
constexpr int M_  = B_ * S_;   // 8192

// Scratch (device globals — no allocation allowed)
__device__ __half g_xq[(size_t)M_ * D_];   // fp16 copies of inputs
__device__ __half g_xk[(size_t)M_ * D_];
__device__ __half g_xv[(size_t)M_ * D_];
__device__ __half g_wq[(size_t)D_ * D_];
__device__ __half g_wk[(size_t)D_ * D_];
__device__ __half g_wv[(size_t)D_ * D_];
__device__ __half g_wo[(size_t)D_ * D_];
__device__ __half g_qh[(size_t)B_ * H_ * S_ * DK_];   // proj outputs [B,H,S,DK]
__device__ __half g_kh[(size_t)B_ * H_ * S_ * DK_];
__device__ __half g_vh[(size_t)B_ * H_ * S_ * DK_];
__device__ __half g_ctxh[(size_t)M_ * D_];            // flash output [B,S,D] fp16

// ---------------------------------------------------------------------------
// helpers (all non-suffixed PTX: works under generic sm_103 target)
// ---------------------------------------------------------------------------
__device__ __forceinline__ void mma_f16_16n8k16(float* c, const uint32_t* a,
                                                uint32_t b0, uint32_t b1) {
    asm volatile(
        "mma.sync.aligned.m16n8k16.row.col.f32.f16.f16.f32 "
        "{%0,%1,%2,%3}, {%4,%5,%6,%7}, {%8,%9}, {%0,%1,%2,%3};"
        : "+f"(c[0]), "+f"(c[1]), "+f"(c[2]), "+f"(c[3])
        : "r"(a[0]), "r"(a[1]), "r"(a[2]), "r"(a[3]), "r"(b0), "r"(b1));
}

__device__ __forceinline__ uint32_t smem_u32(const void* p) {
    uint32_t a;
    asm("{ .reg .u64 t; cvta.to.shared.u64 t, %1; cvt.u32.u64 %0, t; }"
        : "=r"(a) : "l"(p));
    return a;
}
__device__ __forceinline__ void cp_async16(uint32_t saddr, const void* g) {
    asm volatile("cp.async.ca.shared.global [%0], [%1], 16;"
                 :: "r"(saddr), "l"(g));
}
#define CP_COMMIT() asm volatile("cp.async.commit_group;" ::: "memory")
#define CP_WAIT0()  asm volatile("cp.async.wait_group 0;" ::: "memory")
#define CP_WAIT1()  asm volatile("cp.async.wait_group 1;" ::: "memory")

__device__ __forceinline__ void ldsm_x4(uint32_t& r0, uint32_t& r1,
                                        uint32_t& r2, uint32_t& r3,
                                        uint32_t addr) {
    asm volatile("ldmatrix.sync.aligned.m8n8.x4.shared.b16 {%0,%1,%2,%3}, [%4];"
                 : "=r"(r0), "=r"(r1), "=r"(r2), "=r"(r3) : "r"(addr));
}
__device__ __forceinline__ void ldsm_x4_trans(uint32_t& r0, uint32_t& r1,
                                              uint32_t& r2, uint32_t& r3,
                                              uint32_t addr) {
    asm volatile("ldmatrix.sync.aligned.m8n8.x4.trans.shared.b16 {%0,%1,%2,%3}, [%4];"
                 : "=r"(r0), "=r"(r1), "=r"(r2), "=r"(r3) : "r"(addr));
}

// ---------------------------------------------------------------------------
// Pre-pass: convert fp32 inputs/weights to fp16 device globals (one rounding,
// same __floats2half2_rn the GEMM fill used to do -> identical values).
// grid = (4096, 7); y selects tensor; W tensors exit early.
// ---------------------------------------------------------------------------
__global__ __launch_bounds__(256) void cvt_f16(
    const float* __restrict__ Q, const float* __restrict__ K,
    const float* __restrict__ V, const float* __restrict__ Wq,
    const float* __restrict__ Wk, const float* __restrict__ Wv,
    const float* __restrict__ Wo)
{
    const int y = blockIdx.y;
    const float* src;
    __half* dst;
    size_t n;
    switch (y) {
        case 0: src = Q;  dst = g_xq; n = (size_t)M_ * D_; break;
        case 1: src = K;  dst = g_xk; n = (size_t)M_ * D_; break;
        case 2: src = V;  dst = g_xv; n = (size_t)M_ * D_; break;
        case 3: src = Wq; dst = g_wq; n = (size_t)D_ * D_; break;
        case 4: src = Wk; dst = g_wk; n = (size_t)D_ * D_; break;
        case 5: src = Wv; dst = g_wv; n = (size_t)D_ * D_; break;
        default: src = Wo; dst = g_wo; n = (size_t)D_ * D_; break;
    }
    size_t i = ((size_t)blockIdx.x * 256 + threadIdx.x) * 8;
    if (i >= n) return;
    float4 a = *(const float4*)(src + i);
    float4 b = *(const float4*)(src + i + 4);
    __half2 h0 = __floats2half2_rn(a.x, a.y);
    __half2 h1 = __floats2half2_rn(a.z, a.w);
    __half2 h2 = __floats2half2_rn(b.x, b.y);
    __half2 h3 = __floats2half2_rn(b.z, b.w);
    uint4 u;
    u.x = *(uint32_t*)&h0; u.y = *(uint32_t*)&h1;
    u.z = *(uint32_t*)&h2; u.w = *(uint32_t*)&h3;
    *(uint4*)(dst + i) = u;
}

// ---------------------------------------------------------------------------
// FP16 GEMM v3: all-fp16 inputs, cp.async 3-stage pipeline, BK=32, zero cvt
// in the main loop. BM=BN=128, 256 threads, 8 warps (4x2), warp tile 32x64.
// Smem rows 64B, XOR swizzle chunk^=((row>>1)&3): ldsm 8-row phases hit
// quads (4r + c')&7 all distinct (verified by enumeration).
// which: 0/1/2 -> read g_xq/g_xk/g_xv, write fp16 split-head;
//        3     -> read g_ctxh, write fp32 dst.   (all device-side symbols)
// ---------------------------------------------------------------------------
constexpr int GROW   = 32;                 // halves per smem row (64 B)
constexpr int GSTAGE = 128 * GROW;         // halves per tensor per stage
constexpr int GSTB   = GSTAGE * 2;         // bytes per tensor per stage (8192)

__global__ __launch_bounds__(256, 2) void gemm_f16(
    const float* __restrict__ bias, float* __restrict__ dst, int which)
{
    __shared__ __half As[3][GSTAGE];
    __shared__ __half Bs[3][GSTAGE];

    const int tid = threadIdx.x;
    const int wid = tid >> 5;
    const int lane = tid & 31;
    const int m0 = blockIdx.y * 128;
    const int n0 = blockIdx.x * 128;
    const int warp_m = (wid & 3) * 32;
    const int warp_n = (wid >> 2) * 64;

    const __half* Ah = (which == 0) ? g_xq : (which == 1) ? g_xk
                     : (which == 2) ? g_xv : g_ctxh;
    const __half* Wh = (which == 0) ? g_wq : (which == 1) ? g_wk
                     : (which == 2) ? g_wv : g_wo;
    const __half* gA = Ah + (size_t)m0 * D_;
    const __half* gB = Wh + (size_t)n0 * D_;

    const uint32_t sAb = smem_u32(&As[0][0]);
    const uint32_t sBb = smem_u32(&Bs[0][0]);

    // Fill: 512 16B-chunks per tensor per stage; 2 per thread.
    auto fill = [&](int st, int t) {
#pragma unroll
        for (int i = 0; i < 2; i++) {
            int idx = tid + i * 256;        // 0..511
            int row = idx >> 2;             // 0..127
            int ch = idx & 3;
            int sch = ch ^ ((row >> 1) & 3);
            uint32_t doff = (uint32_t)(st * GSTB + row * 64 + sch * 16);
            const __half* sa = gA + (size_t)row * D_ + t * 32 + ch * 8;
            const __half* sb = gB + (size_t)row * D_ + t * 32 + ch * 8;
            cp_async16(sAb + doff, sa);
            cp_async16(sBb + doff, sb);
        }
        CP_COMMIT();
    };

    float acc[2][8][4];
#pragma unroll
    for (int i = 0; i < 2; i++)
#pragma unroll
        for (int j = 0; j < 8; j++)
#pragma unroll
            for (int r = 0; r < 4; r++) acc[i][j][r] = 0.f;

    // Fragment lane offsets (R14-proven mappings, BK=32 chunk base 2*s2).
    const int lm = lane >> 3;
    const int lr7 = lane & 7;
    const int rA = (lm & 1) * 8 + lr7;
    const int cAh = lm >> 1;
    const int rB = (lm >> 1) * 8 + lr7;
    const int cBh = lm & 1;

    uint32_t aOff[2][2], bOff[4][2];   // [tile][s2] byte offsets within stage
#pragma unroll
    for (int t = 0; t < 2; t++)
#pragma unroll
        for (int s2 = 0; s2 < 2; s2++) {
            int row = warp_m + 16 * t + rA;
            int c = 2 * s2 + cAh;
            aOff[t][s2] = (uint32_t)(row * 64 + ((c ^ ((row >> 1) & 3)) * 16));
        }
#pragma unroll
    for (int jnp = 0; jnp < 4; jnp++)
#pragma unroll
        for (int s2 = 0; s2 < 2; s2++) {
            int row = warp_n + 16 * jnp + rB;
            int c = 2 * s2 + cBh;
            bOff[jnp][s2] = (uint32_t)(row * 64 + ((c ^ ((row >> 1) & 3)) * 16));
        }

    constexpr int T = D_ / 32;   // 32 iterations
    fill(0, 0);
    fill(1, 1);

    int st = 0;
    for (int t = 0; t < T; t++) {
        if (t < T - 1) { CP_WAIT1(); } else { CP_WAIT0(); }
        __syncthreads();
        if (t + 2 < T) {
            int st2 = st + 2; if (st2 >= 3) st2 -= 3;
            fill(st2, t + 2);
        }

        const uint32_t aSt = sAb + (uint32_t)(st * GSTB);
        const uint32_t bSt = sBb + (uint32_t)(st * GSTB);

#pragma unroll
        for (int s2 = 0; s2 < 2; s2++) {
            uint32_t a[2][4];
            ldsm_x4(a[0][0], a[0][1], a[0][2], a[0][3], aSt + aOff[0][s2]);
            ldsm_x4(a[1][0], a[1][1], a[1][2], a[1][3], aSt + aOff[1][s2]);
#pragma unroll
            for (int jnp = 0; jnp < 4; jnp++) {
                uint32_t b0, b1, b2, b3;
                ldsm_x4(b0, b1, b2, b3, bSt + bOff[jnp][s2]);
                mma_f16_16n8k16(acc[0][2 * jnp], a[0], b0, b1);
                mma_f16_16n8k16(acc[1][2 * jnp], a[1], b0, b1);
                mma_f16_16n8k16(acc[0][2 * jnp + 1], a[0], b2, b3);
                mma_f16_16n8k16(acc[1][2 * jnp + 1], a[1], b2, b3);
            }
        }

        if (++st == 3) st = 0;
    }

    const int r8 = lane >> 2;
    const int c2 = (lane & 3) * 2;
#pragma unroll
    for (int im = 0; im < 2; im++) {
#pragma unroll
        for (int jn = 0; jn < 8; jn++) {
            int n = n0 + warp_n + 8 * jn + c2;
            float bx = bias[n], by = bias[n + 1];
            int mA = m0 + warp_m + 16 * im + r8;
            int mB = mA + 8;
            float2 v0 = make_float2(acc[im][jn][0] + bx, acc[im][jn][1] + by);
            float2 v1 = make_float2(acc[im][jn][2] + bx, acc[im][jn][3] + by);
            if (which < 3) {
                __half* outh = (which == 0) ? g_qh : (which == 1) ? g_kh : g_vh;
                __half2 h0 = __floats2half2_rn(v0.x, v0.y);
                __half2 h1 = __floats2half2_rn(v1.x, v1.y);
                int h = n >> 6, dk = n & 63;
                int bA = mA >> 11, sA = mA & (S_ - 1);
                int bB = mB >> 11, sB = mB & (S_ - 1);
                *(__half2*)&outh[(((size_t)(bA * H_ + h) * S_ + sA) << 6) + dk] = h0;
                *(__half2*)&outh[(((size_t)(bB * H_ + h) * S_ + sB) << 6) + dk] = h1;
            } else {
                *(float2*)&dst[(size_t)mA * D_ + n] = v0;
                *(float2*)&dst[(size_t)mB * D_ + n] = v1;
            }
        }
    }
}

// ---------------------------------------------------------------------------
// Flash attention v7 (fp16 m16n8k16, P-in-registers) — R13/R14 proven body.
// ONLY change: epilogue writes fp16 g_ctxh (same rounding the outproj fill
// used to apply -> bitwise-identical downstream values).
// ---------------------------------------------------------------------------
constexpr int QBYTES = 256 * 144;
constexpr int KSTAGE = 64 * 144;
constexpr int VSTAGE = 64 * 144;
constexpr int FSMEM  = QBYTES + 2 * KSTAGE + 2 * VSTAGE;  // 73728

__global__ __launch_bounds__(256, 1) void flash_f16()
{
    extern __shared__ char smc[];
    char* sQ = smc;
    char* sK = sQ + QBYTES;
    char* sV = sK + 2 * KSTAGE;

    const uint32_t sqb = smem_u32(sQ);
    const uint32_t skb = smem_u32(sK);
    const uint32_t svb = smem_u32(sV);

    const int tid = threadIdx.x;
    const int wid = tid >> 5;
    const int lane = tid & 31;
    const int r8 = lane >> 2;
    const int c4 = lane & 3;
    const int lm = lane >> 3;
    const int lr7 = lane & 7;

    const uint32_t laneA =
        (uint32_t)(((lm & 1) * 8 + lr7) * 144 + (lm >> 1) * 16);
    const uint32_t laneB =
        (uint32_t)(((lm >> 1) * 8 + lr7) * 144 + (lm & 1) * 16);
    const uint32_t laneV =
        (uint32_t)(((lm & 1) * 8 + lr7) * 144 + (lm >> 1) * 16);

    const int q0 = blockIdx.x * 256;
    const int h = blockIdx.y;
    const int b = blockIdx.z;
    const size_t base = (size_t)(b * H_ + h) * S_ * DK_;
    const __half* qg = g_qh + base + (size_t)q0 * DK_;
    const __half* kg = g_kh + base;
    const __half* vg = g_vh + base;

    const int wr = wid * 32;

    auto issue_chunk = [&](int kb, int st) {
#pragma unroll
        for (int i = 0; i < 2; i++) {
            int idx = tid + i * 256;
            int row = idx >> 3;
            int c16 = (idx & 7) * 16;
            cp_async16(skb + (uint32_t)(st * KSTAGE + row * 144) + c16,
                       kg + (size_t)(kb + row) * DK_ + (idx & 7) * 8);
            cp_async16(svb + (uint32_t)(st * VSTAGE + row * 144) + c16,
                       vg + (size_t)(kb + row) * DK_ + (idx & 7) * 8);
        }
        CP_COMMIT();
    };

#pragma unroll
    for (int i = 0; i < 8; i++) {
        int idx = tid + i * 256;
        int row = idx >> 3;
        int c16 = (idx & 7) * 16;
        cp_async16(sqb + (uint32_t)(row * 144) + c16,
                   qg + (size_t)row * DK_ + (idx & 7) * 8);
    }
    CP_COMMIT();
    issue_chunk(0, 0);

    CP_WAIT1();
    __syncthreads();

    uint32_t aq[2][4][4];
    {
        const __half2 hs = __half2half2(__float2half_rn(0.125f));
#pragma unroll
        for (int t = 0; t < 2; t++) {
#pragma unroll
            for (int kc = 0; kc < 4; kc++) {
                uint32_t addr = sqb + (uint32_t)((wr + 16 * t) * 144 + kc * 32) + laneA;
                ldsm_x4(aq[t][kc][0], aq[t][kc][1], aq[t][kc][2], aq[t][kc][3], addr);
#pragma unroll
                for (int r = 0; r < 4; r++) {
                    __half2 v = *(__half2*)&aq[t][kc][r];
                    v = __hmul2(v, hs);
                    aq[t][kc][r] = *(uint32_t*)&v;
                }
            }
        }
    }

    float mrow[2][2], lrow[2][2];
    float o0[8][4], o1[8][4];
#pragma unroll
    for (int t = 0; t < 2; t++) {
        mrow[t][0] = mrow[t][1] = -1e30f;
        lrow[t][0] = lrow[t][1] = 0.f;
    }
#pragma unroll
    for (int j = 0; j < 8; j++)
#pragma unroll
        for (int r = 0; r < 4; r++) { o0[j][r] = 0.f; o1[j][r] = 0.f; }

    for (int c = 0; c < S_ / 64; c++) {
        const int st = c & 1;
        CP_WAIT0();
        __syncthreads();
        if (c + 1 < S_ / 64) issue_chunk((c + 1) * 64, st ^ 1);

        const uint32_t skc = skb + (uint32_t)(st * KSTAGE) + laneB;
        const uint32_t svc = svb + (uint32_t)(st * VSTAGE) + laneV;

        float s0[8][4], s1[8][4];
#pragma unroll
        for (int j = 0; j < 8; j++)
#pragma unroll
            for (int r = 0; r < 4; r++) { s0[j][r] = 0.f; s1[j][r] = 0.f; }

#pragma unroll
        for (int kc = 0; kc < 4; kc++) {
#pragma unroll
            for (int jnp = 0; jnp < 4; jnp++) {
                uint32_t k0, k1, k2, k3;
                ldsm_x4(k0, k1, k2, k3,
                        skc + (uint32_t)(jnp * 16 * 144 + kc * 32));
                mma_f16_16n8k16(s0[2 * jnp], aq[0][kc], k0, k1);
                mma_f16_16n8k16(s1[2 * jnp], aq[1][kc], k0, k1);
                mma_f16_16n8k16(s0[2 * jnp + 1], aq[0][kc], k2, k3);
                mma_f16_16n8k16(s1[2 * jnp + 1], aq[1][kc], k2, k3);
            }
        }

        uint32_t ph0[8][2], ph1[8][2];
#pragma unroll
        for (int t = 0; t < 2; t++) {
            float (*s)[4] = (t == 0) ? s0 : s1;
            float (*o)[4] = (t == 0) ? o0 : o1;
            uint32_t (*ph)[2] = (t == 0) ? ph0 : ph1;
            float mx0 = -1e30f, mx1 = -1e30f;
#pragma unroll
            for (int jn = 0; jn < 8; jn++) {
                mx0 = fmaxf(mx0, fmaxf(s[jn][0], s[jn][1]));
                mx1 = fmaxf(mx1, fmaxf(s[jn][2], s[jn][3]));
            }
            mx0 = fmaxf(mx0, __shfl_xor_sync(0xffffffffu, mx0, 1));
            mx0 = fmaxf(mx0, __shfl_xor_sync(0xffffffffu, mx0, 2));
            mx1 = fmaxf(mx1, __shfl_xor_sync(0xffffffffu, mx1, 1));
            mx1 = fmaxf(mx1, __shfl_xor_sync(0xffffffffu, mx1, 2));
            float mn0 = fmaxf(mrow[t][0], mx0), mn1 = fmaxf(mrow[t][1], mx1);
            float alpha0 = __expf(mrow[t][0] - mn0);
            float alpha1 = __expf(mrow[t][1] - mn1);
            float sum0 = 0.f, sum1 = 0.f;
#pragma unroll
            for (int jn = 0; jn < 8; jn++) {
                float e0 = __expf(s[jn][0] - mn0);
                float e1 = __expf(s[jn][1] - mn0);
                float e2 = __expf(s[jn][2] - mn1);
                float e3 = __expf(s[jn][3] - mn1);
                sum0 += e0 + e1;
                sum1 += e2 + e3;
                __half2 hA = __floats2half2_rn(e0, e1);
                __half2 hB = __floats2half2_rn(e2, e3);
                ph[jn][0] = *(uint32_t*)&hA;
                ph[jn][1] = *(uint32_t*)&hB;
            }
            sum0 += __shfl_xor_sync(0xffffffffu, sum0, 1);
            sum0 += __shfl_xor_sync(0xffffffffu, sum0, 2);
            sum1 += __shfl_xor_sync(0xffffffffu, sum1, 1);
            sum1 += __shfl_xor_sync(0xffffffffu, sum1, 2);
            lrow[t][0] = lrow[t][0] * alpha0 + sum0;
            lrow[t][1] = lrow[t][1] * alpha1 + sum1;
            mrow[t][0] = mn0;
            mrow[t][1] = mn1;
#pragma unroll
            for (int jn = 0; jn < 8; jn++) {
                o[jn][0] *= alpha0; o[jn][1] *= alpha0;
                o[jn][2] *= alpha1; o[jn][3] *= alpha1;
            }
        }

#pragma unroll
        for (int kc = 0; kc < 4; kc++) {
            uint32_t ap0[4] = { ph0[2 * kc][0], ph0[2 * kc][1],
                                ph0[2 * kc + 1][0], ph0[2 * kc + 1][1] };
            uint32_t ap1[4] = { ph1[2 * kc][0], ph1[2 * kc][1],
                                ph1[2 * kc + 1][0], ph1[2 * kc + 1][1] };
#pragma unroll
            for (int jnp = 0; jnp < 4; jnp++) {
                uint32_t v0, v1, v2, v3;
                ldsm_x4_trans(v0, v1, v2, v3,
                              svc + (uint32_t)(kc * 16 * 144 + jnp * 32));
                mma_f16_16n8k16(o0[2 * jnp], ap0, v0, v1);
                mma_f16_16n8k16(o1[2 * jnp], ap1, v0, v1);
                mma_f16_16n8k16(o0[2 * jnp + 1], ap0, v2, v3);
                mma_f16_16n8k16(o1[2 * jnp + 1], ap1, v2, v3);
            }
        }
    }

    // ---- epilogue: normalize + write ctx [B,S,D] as fp16 ----
#pragma unroll
    for (int t = 0; t < 2; t++) {
        float (*o)[4] = (t == 0) ? o0 : o1;
        float inv0 = 1.0f / lrow[t][0], inv1 = 1.0f / lrow[t][1];
        int row0 = q0 + wr + 16 * t + r8;
        int row1 = row0 + 8;
        size_t g0 = ((size_t)b * S_ + row0) * D_ + h * DK_;
        size_t g1 = ((size_t)b * S_ + row1) * D_ + h * DK_;
#pragma unroll
        for (int jn = 0; jn < 8; jn++) {
            int col = 8 * jn + 2 * c4;
            *(__half2*)&g_ctxh[g0 + col] =
                __floats2half2_rn(o[jn][0] * inv0, o[jn][1] * inv0);
            *(__half2*)&g_ctxh[g1 + col] =
                __floats2half2_rn(o[jn][2] * inv1, o[jn][3] * inv1);
        }
    }
}

// ---------------------------------------------------------------------------
// Launch
// ---------------------------------------------------------------------------
extern "C" void kernel_launch(void* const* d_in, const int* in_sizes, int n_in,
                              void* d_out, int out_size)
{
    const float* Q  = (const float*)d_in[0];
    const float* K  = (const float*)d_in[1];
    const float* V  = (const float*)d_in[2];
    const float* Wq = (const float*)d_in[3];
    const float* bq = (const float*)d_in[4];
    const float* Wk = (const float*)d_in[5];
    const float* bk = (const float*)d_in[6];
    const float* Wv = (const float*)d_in[7];
    const float* bv = (const float*)d_in[8];
    const float* Wo = (const float*)d_in[9];
    const float* bo = (const float*)d_in[10];
    float* out = (float*)d_out;

    cudaFuncSetAttribute(flash_f16,
                         cudaFuncAttributeMaxDynamicSharedMemorySize, FSMEM);

    // Pre-pass: fp32 -> fp16 for inputs + weights (grid.y selects tensor).
    cvt_f16<<<dim3(4096, 7), 256>>>(Q, K, V, Wq, Wk, Wv, Wo);

    dim3 ggrid(D_ / 128, M_ / 128);   // (8, 64)
    gemm_f16<<<ggrid, 256>>>(bq, nullptr, 0);
    gemm_f16<<<ggrid, 256>>>(bk, nullptr, 1);
    gemm_f16<<<ggrid, 256>>>(bv, nullptr, 2);

    flash_f16<<<dim3(S_ / 256, H_, B_), 256, FSMEM>>>();

    gemm_f16<<<ggrid, 256>>>(bo, out, 3);
}

// round 16
// speedup vs baseline: 1.9443x; 1.0745x over previous
#include <cuda_runtime.h>
#include <cuda_fp16.h>
#include <cstdint>
#include <math.h>

// Problem constants
constexpr int B_  = 4;
constexpr int S_  = 2048;
constexpr int D_  = 1024;
constexpr int H_  = 16;
constexpr int DK_ = 64;
constexpr int M_  = B_ * S_;   // 8192

// Scratch (device globals — no allocation allowed)
__device__ __half g_xq[(size_t)M_ * D_];   // fp16 copies of inputs
__device__ __half g_xk[(size_t)M_ * D_];
__device__ __half g_xv[(size_t)M_ * D_];
__device__ __half g_wq[(size_t)D_ * D_];
__device__ __half g_wk[(size_t)D_ * D_];
__device__ __half g_wv[(size_t)D_ * D_];
__device__ __half g_wo[(size_t)D_ * D_];
__device__ __half g_qh[(size_t)B_ * H_ * S_ * DK_];   // proj outputs [B,H,S,DK]
__device__ __half g_kh[(size_t)B_ * H_ * S_ * DK_];
__device__ __half g_vh[(size_t)B_ * H_ * S_ * DK_];
__device__ __half g_ctxh[(size_t)M_ * D_];            // flash output [B,S,D] fp16

// ---------------------------------------------------------------------------
// helpers (all non-suffixed PTX: works under generic sm_103 target)
// ---------------------------------------------------------------------------
__device__ __forceinline__ void mma_f16_16n8k16(float* c, const uint32_t* a,
                                                uint32_t b0, uint32_t b1) {
    asm volatile(
        "mma.sync.aligned.m16n8k16.row.col.f32.f16.f16.f32 "
        "{%0,%1,%2,%3}, {%4,%5,%6,%7}, {%8,%9}, {%0,%1,%2,%3};"
        : "+f"(c[0]), "+f"(c[1]), "+f"(c[2]), "+f"(c[3])
        : "r"(a[0]), "r"(a[1]), "r"(a[2]), "r"(a[3]), "r"(b0), "r"(b1));
}

__device__ __forceinline__ uint32_t smem_u32(const void* p) {
    uint32_t a;
    asm("{ .reg .u64 t; cvta.to.shared.u64 t, %1; cvt.u32.u64 %0, t; }"
        : "=r"(a) : "l"(p));
    return a;
}
__device__ __forceinline__ void cp_async16(uint32_t saddr, const void* g) {
    asm volatile("cp.async.ca.shared.global [%0], [%1], 16;"
                 :: "r"(saddr), "l"(g));
}
#define CP_COMMIT() asm volatile("cp.async.commit_group;" ::: "memory")
#define CP_WAIT0()  asm volatile("cp.async.wait_group 0;" ::: "memory")
#define CP_WAIT1()  asm volatile("cp.async.wait_group 1;" ::: "memory")

__device__ __forceinline__ void ldsm_x4(uint32_t& r0, uint32_t& r1,
                                        uint32_t& r2, uint32_t& r3,
                                        uint32_t addr) {
    asm volatile("ldmatrix.sync.aligned.m8n8.x4.shared.b16 {%0,%1,%2,%3}, [%4];"
                 : "=r"(r0), "=r"(r1), "=r"(r2), "=r"(r3) : "r"(addr));
}
__device__ __forceinline__ void ldsm_x4_trans(uint32_t& r0, uint32_t& r1,
                                              uint32_t& r2, uint32_t& r3,
                                              uint32_t addr) {
    asm volatile("ldmatrix.sync.aligned.m8n8.x4.trans.shared.b16 {%0,%1,%2,%3}, [%4];"
                 : "=r"(r0), "=r"(r1), "=r"(r2), "=r"(r3) : "r"(addr));
}

// ---------------------------------------------------------------------------
// Pre-pass: fp32 -> fp16 for inputs + weights (unchanged from R15, proven).
// ---------------------------------------------------------------------------
__global__ __launch_bounds__(256) void cvt_f16(
    const float* __restrict__ Q, const float* __restrict__ K,
    const float* __restrict__ V, const float* __restrict__ Wq,
    const float* __restrict__ Wk, const float* __restrict__ Wv,
    const float* __restrict__ Wo)
{
    const int y = blockIdx.y;
    const float* src;
    __half* dst;
    size_t n;
    switch (y) {
        case 0: src = Q;  dst = g_xq; n = (size_t)M_ * D_; break;
        case 1: src = K;  dst = g_xk; n = (size_t)M_ * D_; break;
        case 2: src = V;  dst = g_xv; n = (size_t)M_ * D_; break;
        case 3: src = Wq; dst = g_wq; n = (size_t)D_ * D_; break;
        case 4: src = Wk; dst = g_wk; n = (size_t)D_ * D_; break;
        case 5: src = Wv; dst = g_wv; n = (size_t)D_ * D_; break;
        default: src = Wo; dst = g_wo; n = (size_t)D_ * D_; break;
    }
    size_t i = ((size_t)blockIdx.x * 256 + threadIdx.x) * 8;
    if (i >= n) return;
    float4 a = *(const float4*)(src + i);
    float4 b = *(const float4*)(src + i + 4);
    __half2 h0 = __floats2half2_rn(a.x, a.y);
    __half2 h1 = __floats2half2_rn(a.z, a.w);
    __half2 h2 = __floats2half2_rn(b.x, b.y);
    __half2 h3 = __floats2half2_rn(b.z, b.w);
    uint4 u;
    u.x = *(uint32_t*)&h0; u.y = *(uint32_t*)&h1;
    u.z = *(uint32_t*)&h2; u.w = *(uint32_t*)&h3;
    *(uint4*)(dst + i) = u;
}

// ---------------------------------------------------------------------------
// FP16 GEMM v3 (R15 body, proven 70.5us) with gridDim.z tensor select:
// which = which_base + blockIdx.z. QKV projections fuse into ONE launch
// (z=0/1/2), removing two partial tail waves.
// ---------------------------------------------------------------------------
constexpr int GROW   = 32;
constexpr int GSTAGE = 128 * GROW;
constexpr int GSTB   = GSTAGE * 2;

__global__ __launch_bounds__(256, 2) void gemm_f16(
    const float* __restrict__ b0p, const float* __restrict__ b1p,
    const float* __restrict__ b2p, float* __restrict__ dst, int which_base)
{
    __shared__ __half As[3][GSTAGE];
    __shared__ __half Bs[3][GSTAGE];

    const int z = blockIdx.z;
    const int which = which_base + z;
    const float* bias = (z == 0) ? b0p : (z == 1) ? b1p : b2p;

    const int tid = threadIdx.x;
    const int wid = tid >> 5;
    const int lane = tid & 31;
    const int m0 = blockIdx.y * 128;
    const int n0 = blockIdx.x * 128;
    const int warp_m = (wid & 3) * 32;
    const int warp_n = (wid >> 2) * 64;

    const __half* Ah = (which == 0) ? g_xq : (which == 1) ? g_xk
                     : (which == 2) ? g_xv : g_ctxh;
    const __half* Wh = (which == 0) ? g_wq : (which == 1) ? g_wk
                     : (which == 2) ? g_wv : g_wo;
    const __half* gA = Ah + (size_t)m0 * D_;
    const __half* gB = Wh + (size_t)n0 * D_;

    const uint32_t sAb = smem_u32(&As[0][0]);
    const uint32_t sBb = smem_u32(&Bs[0][0]);

    auto fill = [&](int st, int t) {
#pragma unroll
        for (int i = 0; i < 2; i++) {
            int idx = tid + i * 256;
            int row = idx >> 2;
            int ch = idx & 3;
            int sch = ch ^ ((row >> 1) & 3);
            uint32_t doff = (uint32_t)(st * GSTB + row * 64 + sch * 16);
            const __half* sa = gA + (size_t)row * D_ + t * 32 + ch * 8;
            const __half* sb = gB + (size_t)row * D_ + t * 32 + ch * 8;
            cp_async16(sAb + doff, sa);
            cp_async16(sBb + doff, sb);
        }
        CP_COMMIT();
    };

    float acc[2][8][4];
#pragma unroll
    for (int i = 0; i < 2; i++)
#pragma unroll
        for (int j = 0; j < 8; j++)
#pragma unroll
            for (int r = 0; r < 4; r++) acc[i][j][r] = 0.f;

    const int lm = lane >> 3;
    const int lr7 = lane & 7;
    const int rA = (lm & 1) * 8 + lr7;
    const int cAh = lm >> 1;
    const int rB = (lm >> 1) * 8 + lr7;
    const int cBh = lm & 1;

    uint32_t aOff[2][2], bOff[4][2];
#pragma unroll
    for (int t = 0; t < 2; t++)
#pragma unroll
        for (int s2 = 0; s2 < 2; s2++) {
            int row = warp_m + 16 * t + rA;
            int c = 2 * s2 + cAh;
            aOff[t][s2] = (uint32_t)(row * 64 + ((c ^ ((row >> 1) & 3)) * 16));
        }
#pragma unroll
    for (int jnp = 0; jnp < 4; jnp++)
#pragma unroll
        for (int s2 = 0; s2 < 2; s2++) {
            int row = warp_n + 16 * jnp + rB;
            int c = 2 * s2 + cBh;
            bOff[jnp][s2] = (uint32_t)(row * 64 + ((c ^ ((row >> 1) & 3)) * 16));
        }

    constexpr int T = D_ / 32;
    fill(0, 0);
    fill(1, 1);

    int st = 0;
    for (int t = 0; t < T; t++) {
        if (t < T - 1) { CP_WAIT1(); } else { CP_WAIT0(); }
        __syncthreads();
        if (t + 2 < T) {
            int st2 = st + 2; if (st2 >= 3) st2 -= 3;
            fill(st2, t + 2);
        }

        const uint32_t aSt = sAb + (uint32_t)(st * GSTB);
        const uint32_t bSt = sBb + (uint32_t)(st * GSTB);

#pragma unroll
        for (int s2 = 0; s2 < 2; s2++) {
            uint32_t a[2][4];
            ldsm_x4(a[0][0], a[0][1], a[0][2], a[0][3], aSt + aOff[0][s2]);
            ldsm_x4(a[1][0], a[1][1], a[1][2], a[1][3], aSt + aOff[1][s2]);
#pragma unroll
            for (int jnp = 0; jnp < 4; jnp++) {
                uint32_t b0, b1, b2, b3;
                ldsm_x4(b0, b1, b2, b3, bSt + bOff[jnp][s2]);
                mma_f16_16n8k16(acc[0][2 * jnp], a[0], b0, b1);
                mma_f16_16n8k16(acc[1][2 * jnp], a[1], b0, b1);
                mma_f16_16n8k16(acc[0][2 * jnp + 1], a[0], b2, b3);
                mma_f16_16n8k16(acc[1][2 * jnp + 1], a[1], b2, b3);
            }
        }

        if (++st == 3) st = 0;
    }

    const int r8 = lane >> 2;
    const int c2 = (lane & 3) * 2;
#pragma unroll
    for (int im = 0; im < 2; im++) {
#pragma unroll
        for (int jn = 0; jn < 8; jn++) {
            int n = n0 + warp_n + 8 * jn + c2;
            float bx = bias[n], by = bias[n + 1];
            int mA = m0 + warp_m + 16 * im + r8;
            int mB = mA + 8;
            float2 v0 = make_float2(acc[im][jn][0] + bx, acc[im][jn][1] + by);
            float2 v1 = make_float2(acc[im][jn][2] + bx, acc[im][jn][3] + by);
            if (which < 3) {
                __half* outh = (which == 0) ? g_qh : (which == 1) ? g_kh : g_vh;
                __half2 h0 = __floats2half2_rn(v0.x, v0.y);
                __half2 h1 = __floats2half2_rn(v1.x, v1.y);
                int h = n >> 6, dk = n & 63;
                int bA = mA >> 11, sA = mA & (S_ - 1);
                int bB = mB >> 11, sB = mB & (S_ - 1);
                *(__half2*)&outh[(((size_t)(bA * H_ + h) * S_ + sA) << 6) + dk] = h0;
                *(__half2*)&outh[(((size_t)(bB * H_ + h) * S_ + sB) << 6) + dk] = h1;
            } else {
                *(float2*)&dst[(size_t)mA * D_ + n] = v0;
                *(float2*)&dst[(size_t)mB * D_ + n] = v1;
            }
        }
    }
}

// ---------------------------------------------------------------------------
// Flash attention v8: BQ=128 (1 m-tile per warp), 2 CTAs/SM.
// Rationale: L1 no longer binds (32% in v7); latency does (2 warps/SMSP).
// Halving per-warp state (regs ~123 < 128) + smem (55KB) doubles occupancy.
// Same arithmetic order per q-row -> rel_err unchanged.
// ---------------------------------------------------------------------------
constexpr int QBYTES = 128 * 144;      // 18432
constexpr int KSTAGE = 64 * 144;       // 9216
constexpr int VSTAGE = 64 * 144;
constexpr int FSMEM  = QBYTES + 2 * KSTAGE + 2 * VSTAGE;  // 55296

__global__ __launch_bounds__(256, 2) void flash_f16()
{
    extern __shared__ char smc[];
    char* sQ = smc;
    char* sK = sQ + QBYTES;
    char* sV = sK + 2 * KSTAGE;

    const uint32_t sqb = smem_u32(sQ);
    const uint32_t skb = smem_u32(sK);
    const uint32_t svb = smem_u32(sV);

    const int tid = threadIdx.x;
    const int wid = tid >> 5;
    const int lane = tid & 31;
    const int r8 = lane >> 2;
    const int c4 = lane & 3;
    const int lm = lane >> 3;
    const int lr7 = lane & 7;

    const uint32_t laneA =
        (uint32_t)(((lm & 1) * 8 + lr7) * 144 + (lm >> 1) * 16);
    const uint32_t laneB =
        (uint32_t)(((lm >> 1) * 8 + lr7) * 144 + (lm & 1) * 16);
    const uint32_t laneV =
        (uint32_t)(((lm & 1) * 8 + lr7) * 144 + (lm >> 1) * 16);

    const int q0 = blockIdx.x * 128;
    const int h = blockIdx.y;
    const int b = blockIdx.z;
    const size_t base = (size_t)(b * H_ + h) * S_ * DK_;
    const __half* qg = g_qh + base + (size_t)q0 * DK_;
    const __half* kg = g_kh + base;
    const __half* vg = g_vh + base;

    const int wr = wid * 16;   // warp's 16 q rows

    auto issue_chunk = [&](int kb, int st) {
#pragma unroll
        for (int i = 0; i < 2; i++) {
            int idx = tid + i * 256;
            int row = idx >> 3;
            int c16 = (idx & 7) * 16;
            cp_async16(skb + (uint32_t)(st * KSTAGE + row * 144) + c16,
                       kg + (size_t)(kb + row) * DK_ + (idx & 7) * 8);
            cp_async16(svb + (uint32_t)(st * VSTAGE + row * 144) + c16,
                       vg + (size_t)(kb + row) * DK_ + (idx & 7) * 8);
        }
        CP_COMMIT();
    };

    // Q fill: 128 rows x 8 chunks = 1024 cp.async, 4 per thread.
#pragma unroll
    for (int i = 0; i < 4; i++) {
        int idx = tid + i * 256;
        int row = idx >> 3;
        int c16 = (idx & 7) * 16;
        cp_async16(sqb + (uint32_t)(row * 144) + c16,
                   qg + (size_t)row * DK_ + (idx & 7) * 8);
    }
    CP_COMMIT();
    issue_chunk(0, 0);

    CP_WAIT1();
    __syncthreads();

    // Q A-fragments, pre-scaled by 0.125 (exact in fp16).
    uint32_t aq[4][4];
    {
        const __half2 hs = __half2half2(__float2half_rn(0.125f));
#pragma unroll
        for (int kc = 0; kc < 4; kc++) {
            uint32_t addr = sqb + (uint32_t)(wr * 144 + kc * 32) + laneA;
            ldsm_x4(aq[kc][0], aq[kc][1], aq[kc][2], aq[kc][3], addr);
#pragma unroll
            for (int r = 0; r < 4; r++) {
                __half2 v = *(__half2*)&aq[kc][r];
                v = __hmul2(v, hs);
                aq[kc][r] = *(uint32_t*)&v;
            }
        }
    }

    float m0r = -1e30f, m1r = -1e30f, l0 = 0.f, l1 = 0.f;
    float o[8][4];
#pragma unroll
    for (int j = 0; j < 8; j++)
#pragma unroll
        for (int r = 0; r < 4; r++) o[j][r] = 0.f;

    for (int c = 0; c < S_ / 64; c++) {
        const int st = c & 1;
        CP_WAIT0();
        __syncthreads();
        if (c + 1 < S_ / 64) issue_chunk((c + 1) * 64, st ^ 1);

        const uint32_t skc = skb + (uint32_t)(st * KSTAGE) + laneB;
        const uint32_t svc = svb + (uint32_t)(st * VSTAGE) + laneV;

        // ---- S = Q K^T ----
        float s[8][4];
#pragma unroll
        for (int j = 0; j < 8; j++)
#pragma unroll
            for (int r = 0; r < 4; r++) s[j][r] = 0.f;

#pragma unroll
        for (int kc = 0; kc < 4; kc++) {
#pragma unroll
            for (int jnp = 0; jnp < 4; jnp++) {
                uint32_t k0, k1, k2, k3;
                ldsm_x4(k0, k1, k2, k3,
                        skc + (uint32_t)(jnp * 16 * 144 + kc * 32));
                mma_f16_16n8k16(s[2 * jnp], aq[kc], k0, k1);
                mma_f16_16n8k16(s[2 * jnp + 1], aq[kc], k2, k3);
            }
        }

        // ---- online softmax; pack P into A-fragments ----
        uint32_t ph[8][2];
        {
            float mx0 = -1e30f, mx1 = -1e30f;
#pragma unroll
            for (int jn = 0; jn < 8; jn++) {
                mx0 = fmaxf(mx0, fmaxf(s[jn][0], s[jn][1]));
                mx1 = fmaxf(mx1, fmaxf(s[jn][2], s[jn][3]));
            }
            mx0 = fmaxf(mx0, __shfl_xor_sync(0xffffffffu, mx0, 1));
            mx0 = fmaxf(mx0, __shfl_xor_sync(0xffffffffu, mx0, 2));
            mx1 = fmaxf(mx1, __shfl_xor_sync(0xffffffffu, mx1, 1));
            mx1 = fmaxf(mx1, __shfl_xor_sync(0xffffffffu, mx1, 2));
            float mn0 = fmaxf(m0r, mx0), mn1 = fmaxf(m1r, mx1);
            float alpha0 = __expf(m0r - mn0);
            float alpha1 = __expf(m1r - mn1);
            float sum0 = 0.f, sum1 = 0.f;
#pragma unroll
            for (int jn = 0; jn < 8; jn++) {
                float e0 = __expf(s[jn][0] - mn0);
                float e1 = __expf(s[jn][1] - mn0);
                float e2 = __expf(s[jn][2] - mn1);
                float e3 = __expf(s[jn][3] - mn1);
                sum0 += e0 + e1;
                sum1 += e2 + e3;
                __half2 hA = __floats2half2_rn(e0, e1);
                __half2 hB = __floats2half2_rn(e2, e3);
                ph[jn][0] = *(uint32_t*)&hA;
                ph[jn][1] = *(uint32_t*)&hB;
            }
            sum0 += __shfl_xor_sync(0xffffffffu, sum0, 1);
            sum0 += __shfl_xor_sync(0xffffffffu, sum0, 2);
            sum1 += __shfl_xor_sync(0xffffffffu, sum1, 1);
            sum1 += __shfl_xor_sync(0xffffffffu, sum1, 2);
            l0 = l0 * alpha0 + sum0;
            l1 = l1 * alpha1 + sum1;
            m0r = mn0;
            m1r = mn1;
#pragma unroll
            for (int jn = 0; jn < 8; jn++) {
                o[jn][0] *= alpha0; o[jn][1] *= alpha0;
                o[jn][2] *= alpha1; o[jn][3] *= alpha1;
            }
        }

        // ---- O += P V ----
#pragma unroll
        for (int kc = 0; kc < 4; kc++) {
            uint32_t ap[4] = { ph[2 * kc][0], ph[2 * kc][1],
                               ph[2 * kc + 1][0], ph[2 * kc + 1][1] };
#pragma unroll
            for (int jnp = 0; jnp < 4; jnp++) {
                uint32_t v0, v1, v2, v3;
                ldsm_x4_trans(v0, v1, v2, v3,
                              svc + (uint32_t)(kc * 16 * 144 + jnp * 32));
                mma_f16_16n8k16(o[2 * jnp], ap, v0, v1);
                mma_f16_16n8k16(o[2 * jnp + 1], ap, v2, v3);
            }
        }
    }

    // ---- epilogue: normalize + write ctx [B,S,D] as fp16 ----
    {
        float inv0 = 1.0f / l0, inv1 = 1.0f / l1;
        int row0 = q0 + wr + r8;
        int row1 = row0 + 8;
        size_t g0 = ((size_t)b * S_ + row0) * D_ + h * DK_;
        size_t g1 = ((size_t)b * S_ + row1) * D_ + h * DK_;
#pragma unroll
        for (int jn = 0; jn < 8; jn++) {
            int col = 8 * jn + 2 * c4;
            *(__half2*)&g_ctxh[g0 + col] =
                __floats2half2_rn(o[jn][0] * inv0, o[jn][1] * inv0);
            *(__half2*)&g_ctxh[g1 + col] =
                __floats2half2_rn(o[jn][2] * inv1, o[jn][3] * inv1);
        }
    }
}

// ---------------------------------------------------------------------------
// Launch
// ---------------------------------------------------------------------------
extern "C" void kernel_launch(void* const* d_in, const int* in_sizes, int n_in,
                              void* d_out, int out_size)
{
    const float* Q  = (const float*)d_in[0];
    const float* K  = (const float*)d_in[1];
    const float* V  = (const float*)d_in[2];
    const float* Wq = (const float*)d_in[3];
    const float* bq = (const float*)d_in[4];
    const float* Wk = (const float*)d_in[5];
    const float* bk = (const float*)d_in[6];
    const float* Wv = (const float*)d_in[7];
    const float* bv = (const float*)d_in[8];
    const float* Wo = (const float*)d_in[9];
    const float* bo = (const float*)d_in[10];
    float* out = (float*)d_out;

    cudaFuncSetAttribute(flash_f16,
                         cudaFuncAttributeMaxDynamicSharedMemorySize, FSMEM);

    cvt_f16<<<dim3(4096, 7), 256>>>(Q, K, V, Wq, Wk, Wv, Wo);

    // Fused QKV projections: one launch, gridDim.z selects Q/K/V.
    gemm_f16<<<dim3(D_ / 128, M_ / 128, 3), 256>>>(bq, bk, bv, nullptr, 0);

    flash_f16<<<dim3(S_ / 128, H_, B_), 256, FSMEM>>>();

    gemm_f16<<<dim3(D_ / 128, M_ / 128, 1), 256>>>(bo, bo, bo, out, 3);
}